// round 1
// baseline (speedup 1.0000x reference)
#include <cuda_runtime.h>

#define NB 8
#define SEQ 2048
#define DH 1024
#define CT 64               // chunk length T
#define NCH (SEQ/CT)        // 32 chunks
#define LRATE 0.01f

// ---------------- scratch (static device globals; no allocation) -------------
__device__ float g_K[NB*SEQ*DH];       // 64 MB
__device__ float g_V[NB*SEQ*DH];       // 64 MB
__device__ float g_Q[NB*SEQ*DH];       // 64 MB
__device__ float g_W[NB*DH*DH];        // 32 MB  per-batch inner weights
__device__ float g_bias[NB*DH];        // per-batch inner bias
__device__ float g_A[NB*NCH*CT*CT];    // 4 MB   k_t·k_s + 1 per chunk
__device__ float g_M[NB*NCH*CT*CT];    // 4 MB   q_t·k_s + 1 per chunk

// ---------------- init: replicate W0/b0 across batches -----------------------
__global__ void init_state_kernel(const float* __restrict__ W0,
                                  const float* __restrict__ b0) {
    int i = blockIdx.x * blockDim.x + threadIdx.x;
    if (i < DH*DH) {
        float w = W0[i];
        #pragma unroll
        for (int b = 0; b < NB; b++) g_W[(long)b*DH*DH + i] = w;
    }
    if (i < DH) {
        float v = b0[i];
        #pragma unroll
        for (int b = 0; b < NB; b++) g_bias[b*DH + i] = v;
    }
}

// ---------------- projections: C[16384,1024] = X @ Theta^T -------------------
// BM=128, BN=64, BK=32, 256 threads, 8x4 microtile per thread.
__global__ __launch_bounds__(256) void proj_kernel(
    const float* __restrict__ X, const float* __restrict__ tK,
    const float* __restrict__ tV, const float* __restrict__ tQ) {
    const float* Th;
    float* Out;
    if (blockIdx.z == 0)      { Th = tK; Out = g_K; }
    else if (blockIdx.z == 1) { Th = tV; Out = g_V; }
    else                      { Th = tQ; Out = g_Q; }

    __shared__ float sX[32*132];   // [k][m] transposed, pitch 132
    __shared__ float sT[32*68];    // [k][n] transposed, pitch 68

    int tid = threadIdx.x;
    int tx = tid & 15, ty = tid >> 4;
    int lr_ = tid >> 3, lq = tid & 7;
    long m0 = (long)blockIdx.x * 128;
    int  n0 = blockIdx.y * 64;

    float acc[8][4];
    #pragma unroll
    for (int i = 0; i < 8; i++)
        #pragma unroll
        for (int j = 0; j < 4; j++) acc[i][j] = 0.f;

    for (int kb = 0; kb < DH; kb += 32) {
        #pragma unroll
        for (int p = 0; p < 4; p++) {
            int m = p*32 + lr_;
            float4 v = *(const float4*)(X + (m0 + m)*DH + kb + lq*4);
            sX[(lq*4+0)*132 + m] = v.x; sX[(lq*4+1)*132 + m] = v.y;
            sX[(lq*4+2)*132 + m] = v.z; sX[(lq*4+3)*132 + m] = v.w;
        }
        #pragma unroll
        for (int p = 0; p < 2; p++) {
            int n = p*32 + lr_;
            float4 v = *(const float4*)(Th + (long)(n0 + n)*DH + kb + lq*4);
            sT[(lq*4+0)*68 + n] = v.x; sT[(lq*4+1)*68 + n] = v.y;
            sT[(lq*4+2)*68 + n] = v.z; sT[(lq*4+3)*68 + n] = v.w;
        }
        __syncthreads();
        #pragma unroll 8
        for (int k = 0; k < 32; k++) {
            float a0[4], a1[4], bb[4];
            *(float4*)a0 = *(const float4*)(sX + k*132 + ty*8);
            *(float4*)a1 = *(const float4*)(sX + k*132 + ty*8 + 4);
            *(float4*)bb = *(const float4*)(sT + k*68 + tx*4);
            #pragma unroll
            for (int i = 0; i < 4; i++)
                #pragma unroll
                for (int j = 0; j < 4; j++) {
                    acc[i][j]   += a0[i]*bb[j];
                    acc[i+4][j] += a1[i]*bb[j];
                }
        }
        __syncthreads();
    }
    #pragma unroll
    for (int i = 0; i < 8; i++) {
        float4 v = make_float4(acc[i][0], acc[i][1], acc[i][2], acc[i][3]);
        *(float4*)(Out + (m0 + ty*8 + i)*DH + n0 + tx*4) = v;
    }
}

// -------- per-chunk attention matrices: A = K Kc^T + 1, M = Q Kc^T + 1 -------
__global__ __launch_bounds__(256) void am_kernel() {
    int c = blockIdx.x, b = blockIdx.y;
    const float* Kc = g_K + ((long)b*SEQ + c*CT)*DH;
    const float* Qc = g_Q + ((long)b*SEQ + c*CT)*DH;
    float* Ao = g_A + (((long)b*NCH + c)*CT)*CT;
    float* Mo = g_M + (((long)b*NCH + c)*CT)*CT;

    __shared__ float sS[32*132];
    __shared__ float sB[32*68];
    int tid = threadIdx.x;
    int tx = tid & 15, ty = tid >> 4;
    int lr_ = tid >> 3, lq = tid & 7;

    float acc[8][4];
    #pragma unroll
    for (int i = 0; i < 8; i++)
        #pragma unroll
        for (int j = 0; j < 4; j++) acc[i][j] = 0.f;

    for (int kb = 0; kb < DH; kb += 32) {
        #pragma unroll
        for (int p = 0; p < 4; p++) {
            int m = p*32 + lr_;
            const float* src = (m < 64) ? (Kc + (long)m*DH) : (Qc + (long)(m-64)*DH);
            float4 v = *(const float4*)(src + kb + lq*4);
            sS[(lq*4+0)*132 + m] = v.x; sS[(lq*4+1)*132 + m] = v.y;
            sS[(lq*4+2)*132 + m] = v.z; sS[(lq*4+3)*132 + m] = v.w;
        }
        #pragma unroll
        for (int p = 0; p < 2; p++) {
            int s = p*32 + lr_;
            float4 v = *(const float4*)(Kc + (long)s*DH + kb + lq*4);
            sB[(lq*4+0)*68 + s] = v.x; sB[(lq*4+1)*68 + s] = v.y;
            sB[(lq*4+2)*68 + s] = v.z; sB[(lq*4+3)*68 + s] = v.w;
        }
        __syncthreads();
        #pragma unroll 8
        for (int k = 0; k < 32; k++) {
            float a0[4], a1[4], bb[4];
            *(float4*)a0 = *(const float4*)(sS + k*132 + ty*8);
            *(float4*)a1 = *(const float4*)(sS + k*132 + ty*8 + 4);
            *(float4*)bb = *(const float4*)(sB + k*68 + tx*4);
            #pragma unroll
            for (int i = 0; i < 4; i++)
                #pragma unroll
                for (int j = 0; j < 4; j++) {
                    acc[i][j]   += a0[i]*bb[j];
                    acc[i+4][j] += a1[i]*bb[j];
                }
        }
        __syncthreads();
    }
    #pragma unroll
    for (int i = 0; i < 8; i++) {
        int t = ty*8 + i;
        float4 v = make_float4(acc[i][0]+1.f, acc[i][1]+1.f, acc[i][2]+1.f, acc[i][3]+1.f);
        if (t < 64) *(float4*)(Ao + (long)t*CT + tx*4) = v;
        else        *(float4*)(Mo + (long)(t-64)*CT + tx*4) = v;
    }
}

// ---------------- chunk step: dual-form TTT update ---------------------------
// grid: (DH/64 row-slices, NB batches), 256 threads, 1 chunk per launch.
#define CHUNK_SMEM_FLOATS (32*132 + 32*68 + 5*64*68 + 64*132 + 64)
#define CHUNK_SMEM_BYTES  (CHUNK_SMEM_FLOATS * 4)

__global__ __launch_bounds__(256) void chunk_kernel(float* __restrict__ out, int c) {
    extern __shared__ float sm[];
    float* sS  = sm;                  // [32][132] stacked K/Q tile (transposed)
    float* sW  = sS + 32*132;         // [32][68]  W tile (transposed)
    float* U   = sW + 32*68;          // [64][68]  c2*(K W^T + b - V)
    float* P   = U  + 64*68;          // [64][68]  Q W^T + b
    float* G   = P  + 64*68;          // [64][68]  solved gradients
    float* A   = G  + 64*68;          // [64][68]  scaled attn (keys)
    float* Mm  = A  + 64*68;          // [64][68]  scaled attn (queries)
    float* sKt = Mm + 64*68;          // [64][132] K chunk j-tile (direct)
    float* bsh = sKt + 64*132;        // [64]

    int b  = blockIdx.y;
    int r0 = blockIdx.x * 64;
    int tid = threadIdx.x;
    int tx = tid & 15, ty = tid >> 4;
    int lr_ = tid >> 3, lq = tid & 7;

    const float* Kc = g_K + ((long)b*SEQ + c*CT)*DH;
    const float* Qc = g_Q + ((long)b*SEQ + c*CT)*DH;
    const float* Vc = g_V + ((long)b*SEQ + c*CT)*DH;
    float* Wp = g_W + ((long)b*DH + r0)*DH;
    float* bp = g_bias + b*DH + r0;

    if (tid < 64) bsh[tid] = bp[tid];

    // ---- phase 1: [U;P] = [Kc;Qc] @ W_slice^T  (M=128, N=64, K=1024) ----
    float acc[8][4];
    #pragma unroll
    for (int i = 0; i < 8; i++)
        #pragma unroll
        for (int j = 0; j < 4; j++) acc[i][j] = 0.f;

    for (int kb = 0; kb < DH; kb += 32) {
        #pragma unroll
        for (int p = 0; p < 4; p++) {
            int m = p*32 + lr_;
            const float* src = (m < 64) ? (Kc + (long)m*DH) : (Qc + (long)(m-64)*DH);
            float4 v = *(const float4*)(src + kb + lq*4);
            sS[(lq*4+0)*132 + m] = v.x; sS[(lq*4+1)*132 + m] = v.y;
            sS[(lq*4+2)*132 + m] = v.z; sS[(lq*4+3)*132 + m] = v.w;
        }
        #pragma unroll
        for (int p = 0; p < 2; p++) {
            int r = p*32 + lr_;
            float4 v = *(const float4*)(Wp + (long)r*DH + kb + lq*4);
            sW[(lq*4+0)*68 + r] = v.x; sW[(lq*4+1)*68 + r] = v.y;
            sW[(lq*4+2)*68 + r] = v.z; sW[(lq*4+3)*68 + r] = v.w;
        }
        __syncthreads();
        #pragma unroll 8
        for (int k = 0; k < 32; k++) {
            float a0[4], a1[4], bb[4];
            *(float4*)a0 = *(const float4*)(sS + k*132 + ty*8);
            *(float4*)a1 = *(const float4*)(sS + k*132 + ty*8 + 4);
            *(float4*)bb = *(const float4*)(sW + k*68 + tx*4);
            #pragma unroll
            for (int i = 0; i < 4; i++)
                #pragma unroll
                for (int j = 0; j < 4; j++) {
                    acc[i][j]   += a0[i]*bb[j];
                    acc[i+4][j] += a1[i]*bb[j];
                }
        }
        __syncthreads();
    }

    const float c2 = 2.0f / (float)DH;
    #pragma unroll
    for (int i = 0; i < 8; i++) {
        int t = ty*8 + i;
        #pragma unroll
        for (int j = 0; j < 4; j++) {
            int r = tx*4 + j;
            if (t < 64) U[t*68 + r] = c2*(acc[i][j] + bsh[r] - Vc[(long)t*DH + r0 + r]);
            else        P[(t-64)*68 + r] = acc[i][j] + bsh[r];
        }
    }
    __syncthreads();

    // ---- load pre-scaled attention matrices ----
    const float cA = c2 * LRATE;
    const float* gA = g_A + (((long)b*NCH + c)*CT)*CT;
    const float* gM = g_M + (((long)b*NCH + c)*CT)*CT;
    for (int idx = tid; idx < 64*64; idx += 256) {
        int t = idx >> 6, s = idx & 63;
        A[t*68 + s]  = cA    * gA[idx];
        Mm[t*68 + s] = LRATE * gM[idx];
    }
    __syncthreads();

    // ---- phase 2: forward substitution, one thread per d_h column ----
    float sumg = 0.f;
    if (tid < 64) {
        int r = tid;
        for (int t = 0; t < 64; t++) {
            float g = U[t*68 + r];
            for (int s = 0; s < t; s++) g -= A[t*68 + s] * G[s*68 + r];
            G[t*68 + r] = g;
            sumg += g;
        }
    }
    __syncthreads();

    // ---- phase 3: Out = P - LR * tril(M) @ G ----
    {
        int r = tid & 63, tg = tid >> 6;
        float* op = out + ((long)b*SEQ + c*CT)*DH + r0 + r;
        #pragma unroll
        for (int mI = 0; mI < 16; mI++) {
            int t = mI*4 + tg;
            float o = P[t*68 + r];
            for (int s = 0; s <= t; s++) o -= Mm[t*68 + s] * G[s*68 + r];
            op[(long)t*DH] = o;
        }
    }
    if (tid < 64) bp[tid] = bsh[tid] - LRATE * sumg;

    // ---- phase 4: W_slice -= LR * G^T @ Kc  (M=64, N=1024 in 8 j-tiles) ----
    for (int jt = 0; jt < 8; jt++) {
        __syncthreads();
        #pragma unroll
        for (int p = 0; p < 8; p++) {
            int t = p*8 + (tid >> 5);
            int q = tid & 31;
            float4 v = *(const float4*)(Kc + (long)t*DH + jt*128 + q*4);
            *(float4*)(sKt + t*132 + q*4) = v;
        }
        __syncthreads();
        float wacc[4][8];
        #pragma unroll
        for (int a = 0; a < 4; a++)
            #pragma unroll
            for (int j = 0; j < 8; j++) wacc[a][j] = 0.f;
        #pragma unroll 8
        for (int t = 0; t < 64; t++) {
            float gg[4], k0[4], k1[4];
            *(float4*)gg = *(const float4*)(G + t*68 + ty*4);
            *(float4*)k0 = *(const float4*)(sKt + t*132 + tx*8);
            *(float4*)k1 = *(const float4*)(sKt + t*132 + tx*8 + 4);
            #pragma unroll
            for (int a = 0; a < 4; a++)
                #pragma unroll
                for (int j = 0; j < 4; j++) {
                    wacc[a][j]   += gg[a]*k0[j];
                    wacc[a][j+4] += gg[a]*k1[j];
                }
        }
        #pragma unroll
        for (int a = 0; a < 4; a++) {
            float* wrow = Wp + (long)(ty*4 + a)*DH + jt*128 + tx*8;
            float4 w0 = *(float4*)wrow;
            float4 w1 = *(float4*)(wrow + 4);
            w0.x -= LRATE*wacc[a][0]; w0.y -= LRATE*wacc[a][1];
            w0.z -= LRATE*wacc[a][2]; w0.w -= LRATE*wacc[a][3];
            w1.x -= LRATE*wacc[a][4]; w1.y -= LRATE*wacc[a][5];
            w1.z -= LRATE*wacc[a][6]; w1.w -= LRATE*wacc[a][7];
            *(float4*)wrow = w0;
            *(float4*)(wrow + 4) = w1;
        }
    }
}

// ---------------- launch ------------------------------------------------------
extern "C" void kernel_launch(void* const* d_in, const int* in_sizes, int n_in,
                              void* d_out, int out_size) {
    const float* in_seq = (const float*)d_in[0];
    const float* tK = (const float*)d_in[1];
    const float* tV = (const float*)d_in[2];
    const float* tQ = (const float*)d_in[3];
    const float* W0 = (const float*)d_in[4];
    const float* b0 = (const float*)d_in[5];
    float* out = (float*)d_out;

    cudaFuncSetAttribute(chunk_kernel,
                         cudaFuncAttributeMaxDynamicSharedMemorySize,
                         CHUNK_SMEM_BYTES);

    init_state_kernel<<<(DH*DH)/256, 256>>>(W0, b0);
    proj_kernel<<<dim3((NB*SEQ)/128, DH/64, 3), 256>>>(in_seq, tK, tV, tQ);
    am_kernel<<<dim3(NCH, NB), 256>>>();
    for (int c = 0; c < NCH; c++)
        chunk_kernel<<<dim3(DH/64, NB), 256, CHUNK_SMEM_BYTES>>>(out, c);
}

// round 2
// speedup vs baseline: 1.2584x; 1.2584x over previous
#include <cuda_runtime.h>

#define NB 8
#define SEQ 2048
#define DH 1024
#define CT 64               // chunk length T
#define NCH (SEQ/CT)        // 32 chunks
#define LRATE 0.01f
#define C2 (2.0f/1024.0f)

// ---------------- scratch (static device globals; no allocation) -------------
__device__ float g_K[NB*SEQ*DH];        // 64 MB
__device__ float g_V[NB*SEQ*DH];        // 64 MB
__device__ float g_Q[NB*SEQ*DH];        // 64 MB
__device__ float g_W[NB*DH*DH];         // 32 MB  per-batch inner weights
__device__ float g_A[NB*NCH*CT*CT];     // 4 MB   cA*(k_t.k_s + 1)  [t][s]
__device__ float g_MT[NB*NCH*CT*CT];    // 4 MB   LR*(q_t.k_s+1) masked, stored [s][t]
__device__ float g_Ti[NB*NCH*CT*CT];    // 4 MB   Tinv stored transposed [s][t]

// ---------------- packed f32x2 helpers ---------------------------------------
typedef unsigned long long ull;

__device__ __forceinline__ void fma2(ull& c, ull a, ull b) {
    asm("fma.rn.f32x2 %0, %1, %2, %0;" : "+l"(c) : "l"(a), "l"(b));
}
__device__ __forceinline__ ull dupf(float a) {
    ull r; asm("mov.b64 %0, {%1, %1};" : "=l"(r) : "f"(a)); return r;
}
__device__ __forceinline__ float2 unpack2(ull v) {
    float2 f; asm("mov.b64 {%0, %1}, %2;" : "=f"(f.x), "=f"(f.y) : "l"(v)); return f;
}

// ---------------- init: replicate W0 across batches --------------------------
__global__ void init_state_kernel(const float* __restrict__ W0) {
    int i = blockIdx.x * blockDim.x + threadIdx.x;
    float w = W0[i];
    #pragma unroll
    for (int b = 0; b < NB; b++) g_W[(long)b*DH*DH + i] = w;
}

// ---------------- projections: C[16384,1024] = X @ Theta^T -------------------
// BM=128, BN=128, BK=16, 256 threads, 8x8 microtile, packed f32x2.
__global__ __launch_bounds__(256) void proj_kernel(
    const float* __restrict__ X, const float* __restrict__ tK,
    const float* __restrict__ tV, const float* __restrict__ tQ) {
    const float* Th;
    float* Out;
    if (blockIdx.z == 0)      { Th = tK; Out = g_K; }
    else if (blockIdx.z == 1) { Th = tV; Out = g_V; }
    else                      { Th = tQ; Out = g_Q; }

    __shared__ float sA[16*132];
    __shared__ float sB[16*132];

    int tid = threadIdx.x;
    int tx = tid & 15, ty = tid >> 4;
    int kq = tid & 3,  mm = tid >> 2;     // loader: kq=float4 idx in k, mm=row
    long m0 = (long)blockIdx.x * 128;
    int  n0 = blockIdx.y * 128;

    ull acc2[8][4];
    #pragma unroll
    for (int i = 0; i < 8; i++)
        #pragma unroll
        for (int j = 0; j < 4; j++) acc2[i][j] = 0ull;

    for (int kb = 0; kb < DH; kb += 16) {
        #pragma unroll
        for (int p = 0; p < 2; p++) {
            int m = p*64 + mm;
            float4 v = *(const float4*)(X + (m0 + m)*DH + kb + kq*4);
            sA[(kq*4+0)*132 + m] = v.x; sA[(kq*4+1)*132 + m] = v.y;
            sA[(kq*4+2)*132 + m] = v.z; sA[(kq*4+3)*132 + m] = v.w;
            float4 w = *(const float4*)(Th + (long)(n0 + m)*DH + kb + kq*4);
            sB[(kq*4+0)*132 + m] = w.x; sB[(kq*4+1)*132 + m] = w.y;
            sB[(kq*4+2)*132 + m] = w.z; sB[(kq*4+3)*132 + m] = w.w;
        }
        __syncthreads();
        #pragma unroll
        for (int k = 0; k < 16; k++) {
            float a[8];
            *(float4*)(a)   = *(const float4*)(sA + k*132 + ty*8);
            *(float4*)(a+4) = *(const float4*)(sA + k*132 + ty*8 + 4);
            ulonglong2 b01 = *(const ulonglong2*)(sB + k*132 + tx*8);
            ulonglong2 b23 = *(const ulonglong2*)(sB + k*132 + tx*8 + 4);
            #pragma unroll
            for (int i = 0; i < 8; i++) {
                ull aa = dupf(a[i]);
                fma2(acc2[i][0], aa, b01.x);
                fma2(acc2[i][1], aa, b01.y);
                fma2(acc2[i][2], aa, b23.x);
                fma2(acc2[i][3], aa, b23.y);
            }
        }
        __syncthreads();
    }
    #pragma unroll
    for (int i = 0; i < 8; i++) {
        float2 c0 = unpack2(acc2[i][0]), c1 = unpack2(acc2[i][1]);
        float2 c2 = unpack2(acc2[i][2]), c3 = unpack2(acc2[i][3]);
        float* dst = Out + (m0 + ty*8 + i)*DH + n0 + tx*8;
        *(float4*)dst       = make_float4(c0.x, c0.y, c1.x, c1.y);
        *(float4*)(dst + 4) = make_float4(c2.x, c2.y, c3.x, c3.y);
    }
}

// -------- per-chunk attn matrices: A = cA*(K Kc^T+1); MT = LR*tril(Q Kc^T+1)^T
__global__ __launch_bounds__(256) void am_kernel() {
    int c = blockIdx.x, b = blockIdx.y;
    const float* Kc = g_K + ((long)b*SEQ + c*CT)*DH;
    const float* Qc = g_Q + ((long)b*SEQ + c*CT)*DH;
    float* Ao = g_A  + (((long)b*NCH + c)*CT)*CT;
    float* Mo = g_MT + (((long)b*NCH + c)*CT)*CT;

    __shared__ float sS[32*132];
    __shared__ float sB[32*68];
    int tid = threadIdx.x;
    int tx = tid & 15, ty = tid >> 4;
    int lr_ = tid >> 3, lq = tid & 7;

    float acc[8][4];
    #pragma unroll
    for (int i = 0; i < 8; i++)
        #pragma unroll
        for (int j = 0; j < 4; j++) acc[i][j] = 0.f;

    for (int kb = 0; kb < DH; kb += 32) {
        #pragma unroll
        for (int p = 0; p < 4; p++) {
            int m = p*32 + lr_;
            const float* src = (m < 64) ? (Kc + (long)m*DH) : (Qc + (long)(m-64)*DH);
            float4 v = *(const float4*)(src + kb + lq*4);
            sS[(lq*4+0)*132 + m] = v.x; sS[(lq*4+1)*132 + m] = v.y;
            sS[(lq*4+2)*132 + m] = v.z; sS[(lq*4+3)*132 + m] = v.w;
        }
        #pragma unroll
        for (int p = 0; p < 2; p++) {
            int s = p*32 + lr_;
            float4 v = *(const float4*)(Kc + (long)s*DH + kb + lq*4);
            sB[(lq*4+0)*68 + s] = v.x; sB[(lq*4+1)*68 + s] = v.y;
            sB[(lq*4+2)*68 + s] = v.z; sB[(lq*4+3)*68 + s] = v.w;
        }
        __syncthreads();
        #pragma unroll 8
        for (int k = 0; k < 32; k++) {
            float a0[4], a1[4], bb[4];
            *(float4*)a0 = *(const float4*)(sS + k*132 + ty*8);
            *(float4*)a1 = *(const float4*)(sS + k*132 + ty*8 + 4);
            *(float4*)bb = *(const float4*)(sB + k*68 + tx*4);
            #pragma unroll
            for (int i = 0; i < 4; i++)
                #pragma unroll
                for (int j = 0; j < 4; j++) {
                    acc[i][j]   += a0[i]*bb[j];
                    acc[i+4][j] += a1[i]*bb[j];
                }
        }
        __syncthreads();
    }
    const float cA = C2 * LRATE;
    #pragma unroll
    for (int i = 0; i < 8; i++) {
        int t = ty*8 + i;
        if (t < 64) {
            float4 v = make_float4(cA*(acc[i][0]+1.f), cA*(acc[i][1]+1.f),
                                   cA*(acc[i][2]+1.f), cA*(acc[i][3]+1.f));
            *(float4*)(Ao + (long)t*CT + tx*4) = v;
        } else {
            int tp = t - 64;
            #pragma unroll
            for (int j = 0; j < 4; j++) {
                int s = tx*4 + j;
                Mo[(long)s*CT + tp] = (s <= tp) ? LRATE*(acc[i][j]+1.f) : 0.f;
            }
        }
    }
}

// -------- Tinv = (I + strict_lower(A))^{-1}, stored transposed [col][row] ----
__global__ __launch_bounds__(64) void tinv_kernel() {
    int c = blockIdx.x, b = blockIdx.y;
    const float* Ai = g_A  + (((long)b*NCH + c)*CT)*CT;
    float*       To = g_Ti + (((long)b*NCH + c)*CT)*CT;

    __shared__ float sL[CT*CT];
    __shared__ float X[CT*(CT+1)];
    int tid = threadIdx.x;        // = column j
    for (int idx = tid; idx < CT*CT; idx += 64) sL[idx] = Ai[idx];
    #pragma unroll
    for (int s = 0; s < CT; s++) X[s*(CT+1) + tid] = (s == tid) ? 1.f : 0.f;
    __syncthreads();

    for (int i = 1; i < CT; i++) {
        float xi = 0.f;
        for (int s = 0; s < i; s++) xi -= sL[i*CT + s] * X[s*(CT+1) + tid];
        if (i > tid) X[i*(CT+1) + tid] = xi;
        __syncthreads();
    }
    for (int i = 0; i < CT; i++)
        To[(long)tid*CT + i] = X[i*(CT+1) + tid];
}

// ---------------- fused persistent chunk kernel ------------------------------
// grid (DH/64 slices, NB batches) = 128 CTAs, 256 threads, loops over 32 chunks.
#define OFF_U  0
#define OFF_P  4352
#define OFF_G  8704
#define OFF_TI 13056
#define OFF_MT 17408
#define OFF_SS 21760          // 32*132 = 4224
#define OFF_SW 25984          // 32*68  = 2176
#define OFF_B  28160          // 64
#define CHUNK_SMEM_FLOATS 28224
#define CHUNK_SMEM_BYTES  (CHUNK_SMEM_FLOATS * 4)
// sKt (64*132 = 8448) aliases U+P region (8704 floats)

__global__ __launch_bounds__(256) void chunk_fused_kernel(
    float* __restrict__ out, const float* __restrict__ b0) {
    extern __shared__ float sm[];
    float* U   = sm + OFF_U;
    float* P   = sm + OFF_P;
    float* G   = sm + OFF_G;
    float* sTi = sm + OFF_TI;
    float* sMT = sm + OFF_MT;
    float* sS  = sm + OFF_SS;
    float* sW  = sm + OFF_SW;
    float* bsh = sm + OFF_B;
    float* sKt = sm + OFF_U;     // alias (phase 4 only)

    int b  = blockIdx.y;
    int r0 = blockIdx.x * 64;
    int tid = threadIdx.x;
    int tx = tid & 15, ty = tid >> 4;
    int lr_ = tid >> 3, lq = tid & 7;

    float* Wp = g_W + ((long)b*DH + r0)*DH;
    if (tid < 64) bsh[tid] = b0[r0 + tid];
    __syncthreads();

    for (int c = 0; c < NCH; c++) {
        const float* Kc = g_K + ((long)b*SEQ + c*CT)*DH;
        const float* Qc = g_Q + ((long)b*SEQ + c*CT)*DH;
        const float* Vc = g_V + ((long)b*SEQ + c*CT)*DH;
        const float* gTi = g_Ti + (((long)b*NCH + c)*CT)*CT;
        const float* gMT = g_MT + (((long)b*NCH + c)*CT)*CT;

        // ---- load Tinv^T and M~^T tiles ----
        for (int idx = tid; idx < CT*CT; idx += 256) {
            int s = idx >> 6, t = idx & 63;
            sTi[s*68 + t] = gTi[idx];
            sMT[s*68 + t] = gMT[idx];
        }

        // ---- phase 1: [U;P](128x64) = [Kc;Qc] @ Wslice^T, packed f32x2 ----
        ull acc2[8][2];
        #pragma unroll
        for (int i = 0; i < 8; i++) { acc2[i][0] = 0ull; acc2[i][1] = 0ull; }

        for (int kb = 0; kb < DH; kb += 32) {
            __syncthreads();
            #pragma unroll
            for (int p = 0; p < 4; p++) {
                int m = p*32 + lr_;
                const float* src = (m < 64) ? (Kc + (long)m*DH) : (Qc + (long)(m-64)*DH);
                float4 v = *(const float4*)(src + kb + lq*4);
                sS[(lq*4+0)*132 + m] = v.x; sS[(lq*4+1)*132 + m] = v.y;
                sS[(lq*4+2)*132 + m] = v.z; sS[(lq*4+3)*132 + m] = v.w;
            }
            #pragma unroll
            for (int p = 0; p < 2; p++) {
                int r = p*32 + lr_;
                float4 v = *(const float4*)(Wp + (long)r*DH + kb + lq*4);
                sW[(lq*4+0)*68 + r] = v.x; sW[(lq*4+1)*68 + r] = v.y;
                sW[(lq*4+2)*68 + r] = v.z; sW[(lq*4+3)*68 + r] = v.w;
            }
            __syncthreads();
            #pragma unroll
            for (int k = 0; k < 32; k++) {
                float a[8];
                *(float4*)(a)   = *(const float4*)(sS + k*132 + ty*8);
                *(float4*)(a+4) = *(const float4*)(sS + k*132 + ty*8 + 4);
                ulonglong2 bq = *(const ulonglong2*)(sW + k*68 + tx*4);
                #pragma unroll
                for (int i = 0; i < 8; i++) {
                    ull aa = dupf(a[i]);
                    fma2(acc2[i][0], aa, bq.x);
                    fma2(acc2[i][1], aa, bq.y);
                }
            }
        }
        __syncthreads();

        // epilogue: U = c2*(KW^T + b - V);  P = QW^T + b
        #pragma unroll
        for (int i = 0; i < 8; i++) {
            int t = ty*8 + i;
            float2 c0 = unpack2(acc2[i][0]), c1 = unpack2(acc2[i][1]);
            float v0 = c0.x, v1 = c0.y, v2 = c1.x, v3 = c1.y;
            int r = tx*4;
            if (t < 64) {
                float4 vv = *(const float4*)(Vc + (long)t*DH + r0 + r);
                U[t*68 + r+0] = C2*(v0 + bsh[r+0] - vv.x);
                U[t*68 + r+1] = C2*(v1 + bsh[r+1] - vv.y);
                U[t*68 + r+2] = C2*(v2 + bsh[r+2] - vv.z);
                U[t*68 + r+3] = C2*(v3 + bsh[r+3] - vv.w);
            } else {
                int tp = t - 64;
                P[tp*68 + r+0] = v0 + bsh[r+0];
                P[tp*68 + r+1] = v1 + bsh[r+1];
                P[tp*68 + r+2] = v2 + bsh[r+2];
                P[tp*68 + r+3] = v3 + bsh[r+3];
            }
        }
        __syncthreads();

        // ---- G = Tinv @ U  (64x64x64 dense, 4x4 microtile) ----
        {
            ull ga[4][2];
            #pragma unroll
            for (int i = 0; i < 4; i++) { ga[i][0] = 0ull; ga[i][1] = 0ull; }
            #pragma unroll 4
            for (int s = 0; s < 64; s++) {
                float a[4];
                *(float4*)a = *(const float4*)(sTi + s*68 + ty*4);
                ulonglong2 bq = *(const ulonglong2*)(U + s*68 + tx*4);
                #pragma unroll
                for (int i = 0; i < 4; i++) {
                    ull aa = dupf(a[i]);
                    fma2(ga[i][0], aa, bq.x);
                    fma2(ga[i][1], aa, bq.y);
                }
            }
            #pragma unroll
            for (int i = 0; i < 4; i++) {
                int t = ty*4 + i;
                float2 c0 = unpack2(ga[i][0]), c1 = unpack2(ga[i][1]);
                *(float4*)(G + t*68 + tx*4) = make_float4(c0.x, c0.y, c1.x, c1.y);
            }
        }
        __syncthreads();

        // ---- out = P - M~ @ G ;  bias -= LR * colsum(G) ----
        {
            ull oa[4][2];
            #pragma unroll
            for (int i = 0; i < 4; i++) { oa[i][0] = 0ull; oa[i][1] = 0ull; }
            #pragma unroll 4
            for (int s = 0; s < 64; s++) {
                float a[4];
                *(float4*)a = *(const float4*)(sMT + s*68 + ty*4);
                ulonglong2 bq = *(const ulonglong2*)(G + s*68 + tx*4);
                #pragma unroll
                for (int i = 0; i < 4; i++) {
                    ull aa = dupf(a[i]);
                    fma2(oa[i][0], aa, bq.x);
                    fma2(oa[i][1], aa, bq.y);
                }
            }
            #pragma unroll
            for (int i = 0; i < 4; i++) {
                int t = ty*4 + i;
                float2 c0 = unpack2(oa[i][0]), c1 = unpack2(oa[i][1]);
                float* op = out + ((long)b*SEQ + c*CT + t)*DH + r0 + tx*4;
                float4 pv = *(const float4*)(P + t*68 + tx*4);
                *(float4*)op = make_float4(pv.x - c0.x, pv.y - c0.y,
                                           pv.z - c1.x, pv.w - c1.y);
            }
            if (tid < 64) {
                float sumg = 0.f;
                #pragma unroll 8
                for (int t = 0; t < 64; t++) sumg += G[t*68 + tid];
                bsh[tid] -= LRATE * sumg;
            }
        }
        __syncthreads();

        // ---- phase 4: Wslice(64x1024) -= LR * G^T @ Kc  (8 col-tiles) ----
        for (int jt = 0; jt < 8; jt++) {
            #pragma unroll
            for (int p = 0; p < 8; p++) {
                int t = p*8 + (tid >> 5);
                int q = tid & 31;
                float4 v = *(const float4*)(Kc + (long)t*DH + jt*128 + q*4);
                *(float4*)(sKt + t*132 + q*4) = v;
            }
            __syncthreads();
            ull wa[4][4];
            #pragma unroll
            for (int a_ = 0; a_ < 4; a_++)
                #pragma unroll
                for (int j = 0; j < 4; j++) wa[a_][j] = 0ull;
            #pragma unroll 4
            for (int t = 0; t < 64; t++) {
                float gg[4];
                *(float4*)gg = *(const float4*)(G + t*68 + ty*4);
                ulonglong2 k01 = *(const ulonglong2*)(sKt + t*132 + tx*8);
                ulonglong2 k23 = *(const ulonglong2*)(sKt + t*132 + tx*8 + 4);
                #pragma unroll
                for (int a_ = 0; a_ < 4; a_++) {
                    ull aa = dupf(gg[a_]);
                    fma2(wa[a_][0], aa, k01.x);
                    fma2(wa[a_][1], aa, k01.y);
                    fma2(wa[a_][2], aa, k23.x);
                    fma2(wa[a_][3], aa, k23.y);
                }
            }
            #pragma unroll
            for (int a_ = 0; a_ < 4; a_++) {
                float* wrow = Wp + (long)(ty*4 + a_)*DH + jt*128 + tx*8;
                float4 w0 = *(float4*)wrow;
                float4 w1 = *(float4*)(wrow + 4);
                float2 c0 = unpack2(wa[a_][0]), c1 = unpack2(wa[a_][1]);
                float2 c2 = unpack2(wa[a_][2]), c3 = unpack2(wa[a_][3]);
                w0.x -= LRATE*c0.x; w0.y -= LRATE*c0.y;
                w0.z -= LRATE*c1.x; w0.w -= LRATE*c1.y;
                w1.x -= LRATE*c2.x; w1.y -= LRATE*c2.y;
                w1.z -= LRATE*c3.x; w1.w -= LRATE*c3.y;
                *(float4*)wrow = w0;
                *(float4*)(wrow + 4) = w1;
            }
            __syncthreads();
        }
        // loop back: phase1 loaders sync before writing sS/sW
    }
}

// ---------------- launch ------------------------------------------------------
extern "C" void kernel_launch(void* const* d_in, const int* in_sizes, int n_in,
                              void* d_out, int out_size) {
    const float* in_seq = (const float*)d_in[0];
    const float* tK = (const float*)d_in[1];
    const float* tV = (const float*)d_in[2];
    const float* tQ = (const float*)d_in[3];
    const float* W0 = (const float*)d_in[4];
    const float* b0 = (const float*)d_in[5];
    float* out = (float*)d_out;

    cudaFuncSetAttribute(chunk_fused_kernel,
                         cudaFuncAttributeMaxDynamicSharedMemorySize,
                         CHUNK_SMEM_BYTES);

    init_state_kernel<<<(DH*DH)/256, 256>>>(W0);
    proj_kernel<<<dim3((NB*SEQ)/128, DH/128, 3), 256>>>(in_seq, tK, tV, tQ);
    am_kernel<<<dim3(NCH, NB), 256>>>();
    tinv_kernel<<<dim3(NCH, NB), 64>>>();
    chunk_fused_kernel<<<dim3(DH/64, NB), 256, CHUNK_SMEM_BYTES>>>(out, b0);
}

// round 4
// speedup vs baseline: 1.5883x; 1.2622x over previous
#include <cuda_runtime.h>
#include <cuda_bf16.h>
#include <cstdint>

#define NB 8
#define SEQ 2048
#define DH 1024
#define CT 64               // chunk length T
#define NCH (SEQ/CT)        // 32 chunks
#define LRATE 0.01f
#define C2 (2.0f/1024.0f)

// ---------------- scratch (static device globals; no allocation) -------------
__device__ float g_K[NB*SEQ*DH];        // 64 MB
__device__ float g_V[NB*SEQ*DH];        // 64 MB
__device__ float g_Q[NB*SEQ*DH];        // 64 MB
__device__ float g_W[NB*DH*DH];         // 32 MB  per-batch inner weights
__device__ float g_A[NB*NCH*CT*CT];     // cA*(k_t.k_s + 1)  [t][s]
__device__ float g_MT[NB*NCH*CT*CT];    // LR*(q_t.k_s+1) masked, stored [s][t]
__device__ float g_Ti[NB*NCH*CT*CT];    // Tinv stored transposed [s][t]
__device__ __nv_bfloat16 g_Xhi[NB*SEQ*DH];
__device__ __nv_bfloat16 g_Xlo[NB*SEQ*DH];
__device__ __nv_bfloat16 g_Thi[3*DH*DH];
__device__ __nv_bfloat16 g_Tlo[3*DH*DH];

// ---------------- packed f32x2 helpers ---------------------------------------
typedef unsigned long long ull;
__device__ __forceinline__ void fma2(ull& c, ull a, ull b) {
    asm("fma.rn.f32x2 %0, %1, %2, %0;" : "+l"(c) : "l"(a), "l"(b));
}
__device__ __forceinline__ ull dupf(float a) {
    ull r; asm("mov.b64 %0, {%1, %1};" : "=l"(r) : "f"(a)); return r;
}
__device__ __forceinline__ float2 unpack2(ull v) {
    float2 f; asm("mov.b64 {%0, %1}, %2;" : "=f"(f.x), "=f"(f.y) : "l"(v)); return f;
}

// ---------------- mma.sync helpers (sm_80-era PTX; safe on this target) ------
__device__ __forceinline__ uint32_t smem_u32(const void* p) {
    uint32_t a;
    asm("{ .reg .u64 t; cvta.to.shared.u64 t, %1; cvt.u32.u64 %0, t; }"
        : "=r"(a) : "l"(p));
    return a;
}
#define SW128(off) ((off) ^ (((off) >> 3) & 0x70))

__device__ __forceinline__ void ldsm_x4(uint32_t& r0, uint32_t& r1,
                                        uint32_t& r2, uint32_t& r3, uint32_t a) {
    asm volatile("ldmatrix.sync.aligned.m8n8.x4.shared.b16 {%0,%1,%2,%3}, [%4];"
                 : "=r"(r0), "=r"(r1), "=r"(r2), "=r"(r3) : "r"(a));
}
__device__ __forceinline__ void ldsm_x2(uint32_t& r0, uint32_t& r1, uint32_t a) {
    asm volatile("ldmatrix.sync.aligned.m8n8.x2.shared.b16 {%0,%1}, [%2];"
                 : "=r"(r0), "=r"(r1) : "r"(a));
}
__device__ __forceinline__ void mma16816(float* c, const uint32_t* a, const uint32_t* b) {
    asm volatile(
        "mma.sync.aligned.m16n8k16.row.col.f32.bf16.bf16.f32 "
        "{%0,%1,%2,%3}, {%4,%5,%6,%7}, {%8,%9}, {%0,%1,%2,%3};"
        : "+f"(c[0]), "+f"(c[1]), "+f"(c[2]), "+f"(c[3])
        : "r"(a[0]), "r"(a[1]), "r"(a[2]), "r"(a[3]), "r"(b[0]), "r"(b[1]));
}
__device__ __forceinline__ void cp16(uint32_t dst, const void* src) {
    asm volatile("cp.async.cg.shared.global [%0], [%1], 16;"
                 :: "r"(dst), "l"(src) : "memory");
}
#define CP_COMMIT() asm volatile("cp.async.commit_group;" ::: "memory")
#define CP_WAIT(n)  asm volatile("cp.async.wait_group %0;" :: "n"(n) : "memory")

// ---------------- convert inputs to bf16 hi/lo --------------------------------
__global__ void cvt_kernel(const float* __restrict__ X, const float* __restrict__ tK,
                           const float* __restrict__ tV, const float* __restrict__ tQ) {
    long i = (long)blockIdx.x * blockDim.x + threadIdx.x;
    if (i < (long)NB*SEQ*DH) {
        float x = X[i];
        __nv_bfloat16 h = __float2bfloat16(x);
        g_Xhi[i] = h;
        g_Xlo[i] = __float2bfloat16(x - __bfloat162float(h));
    }
    if (i < 3L*DH*DH) {
        int z = (int)(i / (DH*DH));
        long r = i - (long)z*DH*DH;
        const float* t = (z == 0) ? tK : (z == 1) ? tV : tQ;
        float x = t[r];
        __nv_bfloat16 h = __float2bfloat16(x);
        g_Thi[i] = h;
        g_Tlo[i] = __float2bfloat16(x - __bfloat162float(h));
    }
}

// ---------------- init: replicate W0 across batches --------------------------
__global__ void init_state_kernel(const float* __restrict__ W0) {
    int i = blockIdx.x * blockDim.x + threadIdx.x;
    float w = W0[i];
    #pragma unroll
    for (int b = 0; b < NB; b++) g_W[(long)b*DH*DH + i] = w;
}

// ------------- mma.sync projection: C[16384,1024] = X @ Theta^T --------------
// BM=128, BN=64, BK=64, 256 thr (8 warps, 4m x 2n), bf16x3 split, cp.async x2.
// Stage layout (bytes): Ahi 16K | Alo 16K | Bhi 8K | Blo 8K  = 48K; 2 stages.
#define PSTG 49152
#define PROJ_SMEM (2*PSTG + 1024)

__global__ __launch_bounds__(256) void proj_mma_kernel() {
    extern __shared__ char psm[];
    uint32_t sb = (smem_u32(psm) + 1023u) & ~1023u;

    int tid = threadIdx.x, lane = tid & 31, wid = tid >> 5;
    int wm = (wid & 3) * 32, wn = (wid >> 2) * 32;
    long m0 = (long)blockIdx.x * 128;
    int  n0 = blockIdx.y * 64;
    int  z  = blockIdx.z;
    const __nv_bfloat16* Th = g_Thi + (long)z*DH*DH;
    const __nv_bfloat16* Tl = g_Tlo + (long)z*DH*DH;
    float* Out = (z == 0) ? g_K : (z == 1) ? g_V : g_Q;

    float c[2][4][4];
    #pragma unroll
    for (int im = 0; im < 2; im++)
        #pragma unroll
        for (int in = 0; in < 4; in++)
            #pragma unroll
            for (int k = 0; k < 4; k++) c[im][in][k] = 0.f;

    // ---- async loader for one k-stage ----
    auto load_stage = [&](int ks, int st) {
        uint32_t base = sb + st*PSTG;
        int kb = ks * 64;           // k offset in elements
        // A hi/lo: 128 rows x 8 chunks of 16B each => 1024 chunks per array
        #pragma unroll
        for (int p = 0; p < 4; p++) {
            int id = tid + p*256;
            int row = id >> 3, ch = id & 7;
            uint32_t off = SW128((uint32_t)(row*128 + ch*16));
            long g = (m0 + row)*DH + kb + ch*8;
            cp16(base + off,         g_Xhi + g);
            cp16(base + 16384 + off, g_Xlo + g);
        }
        // B hi/lo: 64 rows x 8 chunks x 2 arrays = 1024 chunks
        #pragma unroll
        for (int p = 0; p < 4; p++) {
            int id = tid + p*256;
            int arr = id >> 9, rem = id & 511;
            int row = rem >> 3, ch = rem & 7;
            uint32_t off = SW128((uint32_t)(row*128 + ch*16));
            const __nv_bfloat16* src = (arr == 0) ? Th : Tl;
            cp16(base + 32768 + arr*8192 + off,
                 src + (long)(n0 + row)*DH + kb + ch*8);
        }
        CP_COMMIT();
    };

    load_stage(0, 0);
    for (int ks = 0; ks < 16; ks++) {
        int st = ks & 1;
        if (ks + 1 < 16) load_stage(ks + 1, st ^ 1);
        if (ks + 1 < 16) { CP_WAIT(1); } else { CP_WAIT(0); }
        __syncthreads();

        uint32_t Ah = sb + st*PSTG, Al = Ah + 16384;
        uint32_t Bh = Ah + 32768,   Bl = Ah + 40960;
        #pragma unroll
        for (int pass = 0; pass < 3; pass++) {
            uint32_t Ab = (pass == 1) ? Al : Ah;
            uint32_t Bb = (pass == 2) ? Bl : Bh;
            #pragma unroll
            for (int kk = 0; kk < 4; kk++) {
                uint32_t af[2][4];
                #pragma unroll
                for (int im = 0; im < 2; im++) {
                    int t = lane >> 3, ri = lane & 7;
                    int row = wm + im*16 + (t & 1)*8 + ri;
                    uint32_t off = SW128((uint32_t)(row*128 + kk*32 + (t >> 1)*16));
                    ldsm_x4(af[im][0], af[im][1], af[im][2], af[im][3], Ab + off);
                }
                uint32_t bf[4][2];
                #pragma unroll
                for (int in = 0; in < 4; in++) {
                    int l = lane & 15;
                    int t = l >> 3, ni = l & 7;
                    int row = wn + in*8 + ni;
                    uint32_t off = SW128((uint32_t)(row*128 + kk*32 + t*16));
                    ldsm_x2(bf[in][0], bf[in][1], Bb + off);
                }
                #pragma unroll
                for (int im = 0; im < 2; im++)
                    #pragma unroll
                    for (int in = 0; in < 4; in++)
                        mma16816(c[im][in], af[im], bf[in]);
            }
        }
        __syncthreads();
    }

    // ---- epilogue ----
    int grp = lane >> 2, t4 = lane & 3;
    #pragma unroll
    for (int im = 0; im < 2; im++) {
        #pragma unroll
        for (int in = 0; in < 4; in++) {
            long row = m0 + wm + im*16 + grp;
            int col = n0 + wn + in*8 + t4*2;
            *(float2*)(Out + row*DH + col)     = make_float2(c[im][in][0], c[im][in][1]);
            *(float2*)(Out + (row+8)*DH + col) = make_float2(c[im][in][2], c[im][in][3]);
        }
    }
}

// -------- per-chunk attn matrices: A = cA*(K Kc^T+1); MT = LR*tril(Q Kc^T+1)^T
__global__ __launch_bounds__(256) void am_kernel() {
    int c = blockIdx.x, b = blockIdx.y;
    const float* Kc = g_K + ((long)b*SEQ + c*CT)*DH;
    const float* Qc = g_Q + ((long)b*SEQ + c*CT)*DH;
    float* Ao = g_A  + (((long)b*NCH + c)*CT)*CT;
    float* Mo = g_MT + (((long)b*NCH + c)*CT)*CT;

    __shared__ float sS[32*132];
    __shared__ float sB[32*68];
    int tid = threadIdx.x;
    int tx = tid & 15, ty = tid >> 4;
    int lr_ = tid >> 3, lq = tid & 7;

    float acc[8][4];
    #pragma unroll
    for (int i = 0; i < 8; i++)
        #pragma unroll
        for (int j = 0; j < 4; j++) acc[i][j] = 0.f;

    for (int kb = 0; kb < DH; kb += 32) {
        #pragma unroll
        for (int p = 0; p < 4; p++) {
            int m = p*32 + lr_;
            const float* src = (m < 64) ? (Kc + (long)m*DH) : (Qc + (long)(m-64)*DH);
            float4 v = *(const float4*)(src + kb + lq*4);
            sS[(lq*4+0)*132 + m] = v.x; sS[(lq*4+1)*132 + m] = v.y;
            sS[(lq*4+2)*132 + m] = v.z; sS[(lq*4+3)*132 + m] = v.w;
        }
        #pragma unroll
        for (int p = 0; p < 2; p++) {
            int s = p*32 + lr_;
            float4 v = *(const float4*)(Kc + (long)s*DH + kb + lq*4);
            sB[(lq*4+0)*68 + s] = v.x; sB[(lq*4+1)*68 + s] = v.y;
            sB[(lq*4+2)*68 + s] = v.z; sB[(lq*4+3)*68 + s] = v.w;
        }
        __syncthreads();
        #pragma unroll 8
        for (int k = 0; k < 32; k++) {
            float a0[4], a1[4], bb[4];
            *(float4*)a0 = *(const float4*)(sS + k*132 + ty*8);
            *(float4*)a1 = *(const float4*)(sS + k*132 + ty*8 + 4);
            *(float4*)bb = *(const float4*)(sB + k*68 + tx*4);
            #pragma unroll
            for (int i = 0; i < 4; i++)
                #pragma unroll
                for (int j = 0; j < 4; j++) {
                    acc[i][j]   += a0[i]*bb[j];
                    acc[i+4][j] += a1[i]*bb[j];
                }
        }
        __syncthreads();
    }
    const float cA = C2 * LRATE;
    #pragma unroll
    for (int i = 0; i < 8; i++) {
        int t = ty*8 + i;
        if (t < 64) {
            float4 v = make_float4(cA*(acc[i][0]+1.f), cA*(acc[i][1]+1.f),
                                   cA*(acc[i][2]+1.f), cA*(acc[i][3]+1.f));
            *(float4*)(Ao + (long)t*CT + tx*4) = v;
        } else {
            int tp = t - 64;
            #pragma unroll
            for (int j = 0; j < 4; j++) {
                int s = tx*4 + j;
                Mo[(long)s*CT + tp] = (s <= tp) ? LRATE*(acc[i][j]+1.f) : 0.f;
            }
        }
    }
}

// -------- Tinv = (I + strict_lower(A))^{-1}, stored transposed [col][row] ----
__global__ __launch_bounds__(64) void tinv_kernel() {
    int c = blockIdx.x, b = blockIdx.y;
    const float* Ai = g_A  + (((long)b*NCH + c)*CT)*CT;
    float*       To = g_Ti + (((long)b*NCH + c)*CT)*CT;

    __shared__ float sL[CT*CT];
    __shared__ float X[CT*(CT+1)];
    int tid = threadIdx.x;
    for (int idx = tid; idx < CT*CT; idx += 64) sL[idx] = Ai[idx];
    #pragma unroll
    for (int s = 0; s < CT; s++) X[s*(CT+1) + tid] = (s == tid) ? 1.f : 0.f;
    __syncthreads();

    for (int i = 1; i < CT; i++) {
        float xi = 0.f;
        for (int s = 0; s < i; s++) xi -= sL[i*CT + s] * X[s*(CT+1) + tid];
        if (i > tid) X[i*(CT+1) + tid] = xi;
        __syncthreads();
    }
    for (int i = 0; i < CT; i++)
        To[(long)tid*CT + i] = X[i*(CT+1) + tid];
}

// ---------------- fused persistent chunk kernel ------------------------------
#define OFF_U  0
#define OFF_P  4352
#define OFF_G  8704
#define OFF_TI 13056
#define OFF_MT 17408
#define OFF_SS 21760
#define OFF_SW 25984
#define OFF_B  28160
#define CHUNK_SMEM_FLOATS 28224
#define CHUNK_SMEM_BYTES  (CHUNK_SMEM_FLOATS * 4)

__global__ __launch_bounds__(256) void chunk_fused_kernel(
    float* __restrict__ out, const float* __restrict__ b0) {
    extern __shared__ float sm[];
    float* U   = sm + OFF_U;
    float* P   = sm + OFF_P;
    float* G   = sm + OFF_G;
    float* sTi = sm + OFF_TI;
    float* sMT = sm + OFF_MT;
    float* sS  = sm + OFF_SS;
    float* sW  = sm + OFF_SW;
    float* bsh = sm + OFF_B;
    float* sKt = sm + OFF_U;

    int b  = blockIdx.y;
    int r0 = blockIdx.x * 64;
    int tid = threadIdx.x;
    int tx = tid & 15, ty = tid >> 4;
    int lr_ = tid >> 3, lq = tid & 7;

    float* Wp = g_W + ((long)b*DH + r0)*DH;
    if (tid < 64) bsh[tid] = b0[r0 + tid];
    __syncthreads();

    for (int c = 0; c < NCH; c++) {
        const float* Kc = g_K + ((long)b*SEQ + c*CT)*DH;
        const float* Qc = g_Q + ((long)b*SEQ + c*CT)*DH;
        const float* Vc = g_V + ((long)b*SEQ + c*CT)*DH;
        const float* gTi = g_Ti + (((long)b*NCH + c)*CT)*CT;
        const float* gMT = g_MT + (((long)b*NCH + c)*CT)*CT;

        for (int idx = tid; idx < CT*CT; idx += 256) {
            int s = idx >> 6, t = idx & 63;
            sTi[s*68 + t] = gTi[idx];
            sMT[s*68 + t] = gMT[idx];
        }

        ull acc2[8][2];
        #pragma unroll
        for (int i = 0; i < 8; i++) { acc2[i][0] = 0ull; acc2[i][1] = 0ull; }

        for (int kb = 0; kb < DH; kb += 32) {
            __syncthreads();
            #pragma unroll
            for (int p = 0; p < 4; p++) {
                int m = p*32 + lr_;
                const float* src = (m < 64) ? (Kc + (long)m*DH) : (Qc + (long)(m-64)*DH);
                float4 v = *(const float4*)(src + kb + lq*4);
                sS[(lq*4+0)*132 + m] = v.x; sS[(lq*4+1)*132 + m] = v.y;
                sS[(lq*4+2)*132 + m] = v.z; sS[(lq*4+3)*132 + m] = v.w;
            }
            #pragma unroll
            for (int p = 0; p < 2; p++) {
                int r = p*32 + lr_;
                float4 v = *(const float4*)(Wp + (long)r*DH + kb + lq*4);
                sW[(lq*4+0)*68 + r] = v.x; sW[(lq*4+1)*68 + r] = v.y;
                sW[(lq*4+2)*68 + r] = v.z; sW[(lq*4+3)*68 + r] = v.w;
            }
            __syncthreads();
            #pragma unroll
            for (int k = 0; k < 32; k++) {
                float a[8];
                *(float4*)(a)   = *(const float4*)(sS + k*132 + ty*8);
                *(float4*)(a+4) = *(const float4*)(sS + k*132 + ty*8 + 4);
                ulonglong2 bq = *(const ulonglong2*)(sW + k*68 + tx*4);
                #pragma unroll
                for (int i = 0; i < 8; i++) {
                    ull aa = dupf(a[i]);
                    fma2(acc2[i][0], aa, bq.x);
                    fma2(acc2[i][1], aa, bq.y);
                }
            }
        }
        __syncthreads();

        #pragma unroll
        for (int i = 0; i < 8; i++) {
            int t = ty*8 + i;
            float2 c0 = unpack2(acc2[i][0]), c1 = unpack2(acc2[i][1]);
            float v0 = c0.x, v1 = c0.y, v2 = c1.x, v3 = c1.y;
            int r = tx*4;
            if (t < 64) {
                float4 vv = *(const float4*)(Vc + (long)t*DH + r0 + r);
                U[t*68 + r+0] = C2*(v0 + bsh[r+0] - vv.x);
                U[t*68 + r+1] = C2*(v1 + bsh[r+1] - vv.y);
                U[t*68 + r+2] = C2*(v2 + bsh[r+2] - vv.z);
                U[t*68 + r+3] = C2*(v3 + bsh[r+3] - vv.w);
            } else {
                int tp = t - 64;
                P[tp*68 + r+0] = v0 + bsh[r+0];
                P[tp*68 + r+1] = v1 + bsh[r+1];
                P[tp*68 + r+2] = v2 + bsh[r+2];
                P[tp*68 + r+3] = v3 + bsh[r+3];
            }
        }
        __syncthreads();

        {
            ull ga[4][2];
            #pragma unroll
            for (int i = 0; i < 4; i++) { ga[i][0] = 0ull; ga[i][1] = 0ull; }
            #pragma unroll 4
            for (int s = 0; s < 64; s++) {
                float a[4];
                *(float4*)a = *(const float4*)(sTi + s*68 + ty*4);
                ulonglong2 bq = *(const ulonglong2*)(U + s*68 + tx*4);
                #pragma unroll
                for (int i = 0; i < 4; i++) {
                    ull aa = dupf(a[i]);
                    fma2(ga[i][0], aa, bq.x);
                    fma2(ga[i][1], aa, bq.y);
                }
            }
            #pragma unroll
            for (int i = 0; i < 4; i++) {
                int t = ty*4 + i;
                float2 c0 = unpack2(ga[i][0]), c1 = unpack2(ga[i][1]);
                *(float4*)(G + t*68 + tx*4) = make_float4(c0.x, c0.y, c1.x, c1.y);
            }
        }
        __syncthreads();

        {
            ull oa[4][2];
            #pragma unroll
            for (int i = 0; i < 4; i++) { oa[i][0] = 0ull; oa[i][1] = 0ull; }
            #pragma unroll 4
            for (int s = 0; s < 64; s++) {
                float a[4];
                *(float4*)a = *(const float4*)(sMT + s*68 + ty*4);
                ulonglong2 bq = *(const ulonglong2*)(G + s*68 + tx*4);
                #pragma unroll
                for (int i = 0; i < 4; i++) {
                    ull aa = dupf(a[i]);
                    fma2(oa[i][0], aa, bq.x);
                    fma2(oa[i][1], aa, bq.y);
                }
            }
            #pragma unroll
            for (int i = 0; i < 4; i++) {
                int t = ty*4 + i;
                float2 c0 = unpack2(oa[i][0]), c1 = unpack2(oa[i][1]);
                float* op = out + ((long)b*SEQ + c*CT + t)*DH + r0 + tx*4;
                float4 pv = *(const float4*)(P + t*68 + tx*4);
                *(float4*)op = make_float4(pv.x - c0.x, pv.y - c0.y,
                                           pv.z - c1.x, pv.w - c1.y);
            }
            if (tid < 64) {
                float sumg = 0.f;
                #pragma unroll 8
                for (int t = 0; t < 64; t++) sumg += G[t*68 + tid];
                bsh[tid] -= LRATE * sumg;
            }
        }
        __syncthreads();

        for (int jt = 0; jt < 8; jt++) {
            #pragma unroll
            for (int p = 0; p < 8; p++) {
                int t = p*8 + (tid >> 5);
                int q = tid & 31;
                float4 v = *(const float4*)(Kc + (long)t*DH + jt*128 + q*4);
                *(float4*)(sKt + t*132 + q*4) = v;
            }
            __syncthreads();
            ull wa[4][4];
            #pragma unroll
            for (int a_ = 0; a_ < 4; a_++)
                #pragma unroll
                for (int j = 0; j < 4; j++) wa[a_][j] = 0ull;
            #pragma unroll 4
            for (int t = 0; t < 64; t++) {
                float gg[4];
                *(float4*)gg = *(const float4*)(G + t*68 + ty*4);
                ulonglong2 k01 = *(const ulonglong2*)(sKt + t*132 + tx*8);
                ulonglong2 k23 = *(const ulonglong2*)(sKt + t*132 + tx*8 + 4);
                #pragma unroll
                for (int a_ = 0; a_ < 4; a_++) {
                    ull aa = dupf(gg[a_]);
                    fma2(wa[a_][0], aa, k01.x);
                    fma2(wa[a_][1], aa, k01.y);
                    fma2(wa[a_][2], aa, k23.x);
                    fma2(wa[a_][3], aa, k23.y);
                }
            }
            #pragma unroll
            for (int a_ = 0; a_ < 4; a_++) {
                float* wrow = Wp + (long)(ty*4 + a_)*DH + jt*128 + tx*8;
                float4 w0 = *(float4*)wrow;
                float4 w1 = *(float4*)(wrow + 4);
                float2 c0 = unpack2(wa[a_][0]), c1 = unpack2(wa[a_][1]);
                float2 c2 = unpack2(wa[a_][2]), c3 = unpack2(wa[a_][3]);
                w0.x -= LRATE*c0.x; w0.y -= LRATE*c0.y;
                w0.z -= LRATE*c1.x; w0.w -= LRATE*c1.y;
                w1.x -= LRATE*c2.x; w1.y -= LRATE*c2.y;
                w1.z -= LRATE*c3.x; w1.w -= LRATE*c3.y;
                *(float4*)wrow = w0;
                *(float4*)(wrow + 4) = w1;
            }
            __syncthreads();
        }
    }
}

// ---------------- launch ------------------------------------------------------
extern "C" void kernel_launch(void* const* d_in, const int* in_sizes, int n_in,
                              void* d_out, int out_size) {
    const float* in_seq = (const float*)d_in[0];
    const float* tK = (const float*)d_in[1];
    const float* tV = (const float*)d_in[2];
    const float* tQ = (const float*)d_in[3];
    const float* W0 = (const float*)d_in[4];
    const float* b0 = (const float*)d_in[5];
    float* out = (float*)d_out;

    cudaFuncSetAttribute(chunk_fused_kernel,
                         cudaFuncAttributeMaxDynamicSharedMemorySize,
                         CHUNK_SMEM_BYTES);
    cudaFuncSetAttribute(proj_mma_kernel,
                         cudaFuncAttributeMaxDynamicSharedMemorySize,
                         PROJ_SMEM);

    cvt_kernel<<<(NB*SEQ*DH)/256, 256>>>(in_seq, tK, tV, tQ);
    init_state_kernel<<<(DH*DH)/256, 256>>>(W0);
    proj_mma_kernel<<<dim3((NB*SEQ)/128, DH/64, 3), 256, PROJ_SMEM>>>();
    am_kernel<<<dim3(NCH, NB), 256>>>();
    tinv_kernel<<<dim3(NCH, NB), 64>>>();
    chunk_fused_kernel<<<dim3(DH/64, NB), 256, CHUNK_SMEM_BYTES>>>(out, b0);
}

// round 5
// speedup vs baseline: 2.2627x; 1.4246x over previous
#include <cuda_runtime.h>
#include <cuda_bf16.h>
#include <cstdint>

#define NB 8
#define SEQ 2048
#define DH 1024
#define CT 64               // chunk length T
#define NCH (SEQ/CT)        // 32 chunks
#define LRATE 0.01f
#define C2 (2.0f/1024.0f)

// ---------------- scratch (static device globals; no allocation) -------------
__device__ float g_K[NB*SEQ*DH];
__device__ float g_V[NB*SEQ*DH];
__device__ float g_Q[NB*SEQ*DH];
__device__ float g_W[NB*DH*DH];         // fp32 master inner weights
__device__ float g_A[NB*NCH*CT*CT];
__device__ float g_MT[NB*NCH*CT*CT];
__device__ float g_Ti[NB*NCH*CT*CT];
__device__ __nv_bfloat16 g_Xhi[NB*SEQ*DH];
__device__ __nv_bfloat16 g_Xlo[NB*SEQ*DH];
__device__ __nv_bfloat16 g_Thi[3*DH*DH];
__device__ __nv_bfloat16 g_Tlo[3*DH*DH];
__device__ __nv_bfloat16 g_Khi[NB*SEQ*DH];
__device__ __nv_bfloat16 g_Klo[NB*SEQ*DH];
__device__ __nv_bfloat16 g_Qhi[NB*SEQ*DH];
__device__ __nv_bfloat16 g_Qlo[NB*SEQ*DH];
__device__ __nv_bfloat16 g_Whi[NB*DH*DH];
__device__ __nv_bfloat16 g_Wlo[NB*DH*DH];

// ---------------- packed f32x2 helpers ---------------------------------------
typedef unsigned long long ull;
__device__ __forceinline__ void fma2(ull& c, ull a, ull b) {
    asm("fma.rn.f32x2 %0, %1, %2, %0;" : "+l"(c) : "l"(a), "l"(b));
}
__device__ __forceinline__ ull dupf(float a) {
    ull r; asm("mov.b64 %0, {%1, %1};" : "=l"(r) : "f"(a)); return r;
}
__device__ __forceinline__ float2 unpack2(ull v) {
    float2 f; asm("mov.b64 {%0, %1}, %2;" : "=f"(f.x), "=f"(f.y) : "l"(v)); return f;
}

// ---------------- mma.sync helpers -------------------------------------------
__device__ __forceinline__ uint32_t smem_u32(const void* p) {
    uint32_t a;
    asm("{ .reg .u64 t; cvta.to.shared.u64 t, %1; cvt.u32.u64 %0, t; }"
        : "=r"(a) : "l"(p));
    return a;
}
#define SW128(off) ((off) ^ (((off) >> 3) & 0x70))

__device__ __forceinline__ void ldsm_x4(uint32_t& r0, uint32_t& r1,
                                        uint32_t& r2, uint32_t& r3, uint32_t a) {
    asm volatile("ldmatrix.sync.aligned.m8n8.x4.shared.b16 {%0,%1,%2,%3}, [%4];"
                 : "=r"(r0), "=r"(r1), "=r"(r2), "=r"(r3) : "r"(a));
}
__device__ __forceinline__ void ldsm_x2(uint32_t& r0, uint32_t& r1, uint32_t a) {
    asm volatile("ldmatrix.sync.aligned.m8n8.x2.shared.b16 {%0,%1}, [%2];"
                 : "=r"(r0), "=r"(r1) : "r"(a));
}
__device__ __forceinline__ void ldsm_x2t(uint32_t& r0, uint32_t& r1, uint32_t a) {
    asm volatile("ldmatrix.sync.aligned.m8n8.x2.trans.shared.b16 {%0,%1}, [%2];"
                 : "=r"(r0), "=r"(r1) : "r"(a));
}
__device__ __forceinline__ void mma16816(float* c, const uint32_t* a, const uint32_t* b) {
    asm volatile(
        "mma.sync.aligned.m16n8k16.row.col.f32.bf16.bf16.f32 "
        "{%0,%1,%2,%3}, {%4,%5,%6,%7}, {%8,%9}, {%0,%1,%2,%3};"
        : "+f"(c[0]), "+f"(c[1]), "+f"(c[2]), "+f"(c[3])
        : "r"(a[0]), "r"(a[1]), "r"(a[2]), "r"(a[3]), "r"(b[0]), "r"(b[1]));
}
__device__ __forceinline__ void cp16(uint32_t dst, const void* src) {
    asm volatile("cp.async.cg.shared.global [%0], [%1], 16;"
                 :: "r"(dst), "l"(src) : "memory");
}
#define CP_COMMIT() asm volatile("cp.async.commit_group;" ::: "memory")
#define CP_WAIT(n)  asm volatile("cp.async.wait_group %0;" :: "n"(n) : "memory")

// ---------------- convert inputs to bf16 hi/lo --------------------------------
__global__ void cvt_kernel(const float* __restrict__ X, const float* __restrict__ tK,
                           const float* __restrict__ tV, const float* __restrict__ tQ) {
    long i = (long)blockIdx.x * blockDim.x + threadIdx.x;
    if (i < (long)NB*SEQ*DH) {
        float x = X[i];
        __nv_bfloat16 h = __float2bfloat16(x);
        g_Xhi[i] = h;
        g_Xlo[i] = __float2bfloat16(x - __bfloat162float(h));
    }
    if (i < 3L*DH*DH) {
        int z = (int)(i / (DH*DH));
        long r = i - (long)z*DH*DH;
        const float* t = (z == 0) ? tK : (z == 1) ? tV : tQ;
        float x = t[r];
        __nv_bfloat16 h = __float2bfloat16(x);
        g_Thi[i] = h;
        g_Tlo[i] = __float2bfloat16(x - __bfloat162float(h));
    }
}

// ---------------- init: replicate W0 (+hi/lo) across batches -----------------
__global__ void init_state_kernel(const float* __restrict__ W0) {
    int i = blockIdx.x * blockDim.x + threadIdx.x;
    float w = W0[i];
    __nv_bfloat16 h = __float2bfloat16(w);
    __nv_bfloat16 l = __float2bfloat16(w - __bfloat162float(h));
    #pragma unroll
    for (int b = 0; b < NB; b++) {
        g_W  [(long)b*DH*DH + i] = w;
        g_Whi[(long)b*DH*DH + i] = h;
        g_Wlo[(long)b*DH*DH + i] = l;
    }
}

// ------------- mma.sync projection: C[16384,1024] = X @ Theta^T --------------
#define PSTG 49152
#define PROJ_SMEM (2*PSTG + 1024)

__global__ __launch_bounds__(256) void proj_mma_kernel() {
    extern __shared__ char psm[];
    uint32_t sb = (smem_u32(psm) + 1023u) & ~1023u;

    int tid = threadIdx.x, lane = tid & 31, wid = tid >> 5;
    int wm = (wid & 3) * 32, wn = (wid >> 2) * 32;
    long m0 = (long)blockIdx.x * 128;
    int  n0 = blockIdx.y * 64;
    int  z  = blockIdx.z;
    const __nv_bfloat16* Th = g_Thi + (long)z*DH*DH;
    const __nv_bfloat16* Tl = g_Tlo + (long)z*DH*DH;
    float* Out = (z == 0) ? g_K : (z == 1) ? g_V : g_Q;

    float c[2][4][4];
    #pragma unroll
    for (int im = 0; im < 2; im++)
        #pragma unroll
        for (int in = 0; in < 4; in++)
            #pragma unroll
            for (int k = 0; k < 4; k++) c[im][in][k] = 0.f;

    auto load_stage = [&](int ks, int st) {
        uint32_t base = sb + st*PSTG;
        int kb = ks * 64;
        #pragma unroll
        for (int p = 0; p < 4; p++) {
            int id = tid + p*256;
            int row = id >> 3, ch = id & 7;
            uint32_t off = SW128((uint32_t)(row*128 + ch*16));
            long g = (m0 + row)*DH + kb + ch*8;
            cp16(base + off,         g_Xhi + g);
            cp16(base + 16384 + off, g_Xlo + g);
        }
        #pragma unroll
        for (int p = 0; p < 4; p++) {
            int id = tid + p*256;
            int arr = id >> 9, rem = id & 511;
            int row = rem >> 3, ch = rem & 7;
            uint32_t off = SW128((uint32_t)(row*128 + ch*16));
            const __nv_bfloat16* src = (arr == 0) ? Th : Tl;
            cp16(base + 32768 + arr*8192 + off,
                 src + (long)(n0 + row)*DH + kb + ch*8);
        }
        CP_COMMIT();
    };

    load_stage(0, 0);
    for (int ks = 0; ks < 16; ks++) {
        int st = ks & 1;
        if (ks + 1 < 16) load_stage(ks + 1, st ^ 1);
        if (ks + 1 < 16) { CP_WAIT(1); } else { CP_WAIT(0); }
        __syncthreads();

        uint32_t Ah = sb + st*PSTG, Al = Ah + 16384;
        uint32_t Bh = Ah + 32768,   Bl = Ah + 40960;
        #pragma unroll
        for (int pass = 0; pass < 3; pass++) {
            uint32_t Ab = (pass == 1) ? Al : Ah;
            uint32_t Bb = (pass == 2) ? Bl : Bh;
            #pragma unroll
            for (int kk = 0; kk < 4; kk++) {
                uint32_t af[2][4];
                #pragma unroll
                for (int im = 0; im < 2; im++) {
                    int t = lane >> 3, ri = lane & 7;
                    int row = wm + im*16 + (t & 1)*8 + ri;
                    uint32_t off = SW128((uint32_t)(row*128 + kk*32 + (t >> 1)*16));
                    ldsm_x4(af[im][0], af[im][1], af[im][2], af[im][3], Ab + off);
                }
                uint32_t bf[4][2];
                #pragma unroll
                for (int in = 0; in < 4; in++) {
                    int l = lane & 15;
                    int t = l >> 3, ni = l & 7;
                    int row = wn + in*8 + ni;
                    uint32_t off = SW128((uint32_t)(row*128 + kk*32 + t*16));
                    ldsm_x2(bf[in][0], bf[in][1], Bb + off);
                }
                #pragma unroll
                for (int im = 0; im < 2; im++)
                    #pragma unroll
                    for (int in = 0; in < 4; in++)
                        mma16816(c[im][in], af[im], bf[in]);
            }
        }
        __syncthreads();
    }

    // ---- epilogue: fp32 out, plus bf16 hi/lo for K (z=0) and Q (z=2) ----
    __nv_bfloat16* Hout = (z == 0) ? g_Khi : g_Qhi;
    __nv_bfloat16* Lout = (z == 0) ? g_Klo : g_Qlo;
    int grp = lane >> 2, t4 = lane & 3;
    #pragma unroll
    for (int im = 0; im < 2; im++) {
        #pragma unroll
        for (int in = 0; in < 4; in++) {
            long row = m0 + wm + im*16 + grp;
            int col = n0 + wn + in*8 + t4*2;
            #pragma unroll
            for (int h = 0; h < 2; h++) {
                long idx = (row + h*8)*DH + col;
                float x0 = c[im][in][h*2], x1 = c[im][in][h*2+1];
                *(float2*)(Out + idx) = make_float2(x0, x1);
                if (z != 1) {
                    __nv_bfloat16 h0 = __float2bfloat16(x0);
                    __nv_bfloat16 h1 = __float2bfloat16(x1);
                    __nv_bfloat162 hv; hv.x = h0; hv.y = h1;
                    __nv_bfloat162 lv;
                    lv.x = __float2bfloat16(x0 - __bfloat162float(h0));
                    lv.y = __float2bfloat16(x1 - __bfloat162float(h1));
                    *(__nv_bfloat162*)(Hout + idx) = hv;
                    *(__nv_bfloat162*)(Lout + idx) = lv;
                }
            }
        }
    }
}

// -------- per-chunk attn matrices: A = cA*(K Kc^T+1); MT = LR*tril(Q Kc^T+1)^T
__global__ __launch_bounds__(256) void am_kernel() {
    int c = blockIdx.x, b = blockIdx.y;
    const float* Kc = g_K + ((long)b*SEQ + c*CT)*DH;
    const float* Qc = g_Q + ((long)b*SEQ + c*CT)*DH;
    float* Ao = g_A  + (((long)b*NCH + c)*CT)*CT;
    float* Mo = g_MT + (((long)b*NCH + c)*CT)*CT;

    __shared__ float sS[32*132];
    __shared__ float sB[32*68];
    int tid = threadIdx.x;
    int tx = tid & 15, ty = tid >> 4;
    int lr_ = tid >> 3, lq = tid & 7;

    float acc[8][4];
    #pragma unroll
    for (int i = 0; i < 8; i++)
        #pragma unroll
        for (int j = 0; j < 4; j++) acc[i][j] = 0.f;

    for (int kb = 0; kb < DH; kb += 32) {
        #pragma unroll
        for (int p = 0; p < 4; p++) {
            int m = p*32 + lr_;
            const float* src = (m < 64) ? (Kc + (long)m*DH) : (Qc + (long)(m-64)*DH);
            float4 v = *(const float4*)(src + kb + lq*4);
            sS[(lq*4+0)*132 + m] = v.x; sS[(lq*4+1)*132 + m] = v.y;
            sS[(lq*4+2)*132 + m] = v.z; sS[(lq*4+3)*132 + m] = v.w;
        }
        #pragma unroll
        for (int p = 0; p < 2; p++) {
            int s = p*32 + lr_;
            float4 v = *(const float4*)(Kc + (long)s*DH + kb + lq*4);
            sB[(lq*4+0)*68 + s] = v.x; sB[(lq*4+1)*68 + s] = v.y;
            sB[(lq*4+2)*68 + s] = v.z; sB[(lq*4+3)*68 + s] = v.w;
        }
        __syncthreads();
        #pragma unroll 8
        for (int k = 0; k < 32; k++) {
            float a0[4], a1[4], bb[4];
            *(float4*)a0 = *(const float4*)(sS + k*132 + ty*8);
            *(float4*)a1 = *(const float4*)(sS + k*132 + ty*8 + 4);
            *(float4*)bb = *(const float4*)(sB + k*68 + tx*4);
            #pragma unroll
            for (int i = 0; i < 4; i++)
                #pragma unroll
                for (int j = 0; j < 4; j++) {
                    acc[i][j]   += a0[i]*bb[j];
                    acc[i+4][j] += a1[i]*bb[j];
                }
        }
        __syncthreads();
    }
    const float cA = C2 * LRATE;
    #pragma unroll
    for (int i = 0; i < 8; i++) {
        int t = ty*8 + i;
        if (t < 64) {
            float4 v = make_float4(cA*(acc[i][0]+1.f), cA*(acc[i][1]+1.f),
                                   cA*(acc[i][2]+1.f), cA*(acc[i][3]+1.f));
            *(float4*)(Ao + (long)t*CT + tx*4) = v;
        } else {
            int tp = t - 64;
            #pragma unroll
            for (int j = 0; j < 4; j++) {
                int s = tx*4 + j;
                Mo[(long)s*CT + tp] = (s <= tp) ? LRATE*(acc[i][j]+1.f) : 0.f;
            }
        }
    }
}

// -------- Tinv = (I + strict_lower(A))^{-1}, stored transposed [col][row] ----
__global__ __launch_bounds__(64) void tinv_kernel() {
    int c = blockIdx.x, b = blockIdx.y;
    const float* Ai = g_A  + (((long)b*NCH + c)*CT)*CT;
    float*       To = g_Ti + (((long)b*NCH + c)*CT)*CT;

    __shared__ float sL[CT*CT];
    __shared__ float X[CT*(CT+1)];
    int tid = threadIdx.x;
    for (int idx = tid; idx < CT*CT; idx += 64) sL[idx] = Ai[idx];
    #pragma unroll
    for (int s = 0; s < CT; s++) X[s*(CT+1) + tid] = (s == tid) ? 1.f : 0.f;
    __syncthreads();

    for (int i = 1; i < CT; i++) {
        float xi = 0.f;
        for (int s = 0; s < i; s++) xi -= sL[i*CT + s] * X[s*(CT+1) + tid];
        if (i > tid) X[i*(CT+1) + tid] = xi;
        __syncthreads();
    }
    for (int i = 0; i < CT; i++)
        To[(long)tid*CT + i] = X[i*(CT+1) + tid];
}

// ---------------- fused persistent chunk kernel (tensor-core) ----------------
// smem byte offsets
#define OB_U   0u          // fp32 [64][68]
#define OB_P   17408u
#define OB_G   34816u
#define OB_TI  52224u
#define OB_MT  69632u
#define OB_BS  87040u      // 64 floats
#define OB_GTH 87296u      // bf16 Gt hi [64 r][64 t], 128B rows, SW128
#define OB_GTL 95488u
#define OB_STG 104448u     // 2 stages x 48KB
#define ST1    49152u
#define CH_SMEM (104448 + 2*49152)

__global__ __launch_bounds__(256) void chunk_fused_kernel(
    float* __restrict__ out, const float* __restrict__ b0) {
    extern __shared__ char smc[];
    float* smf = (float*)smc;
    float* U   = smf + OB_U/4;
    float* P   = smf + OB_P/4;
    float* G   = smf + OB_G/4;
    float* sTi = smf + OB_TI/4;
    float* sMT = smf + OB_MT/4;
    float* bsh = smf + OB_BS/4;
    uint32_t sb   = smem_u32(smc);
    uint32_t gth  = sb + OB_GTH;
    uint32_t gtl  = sb + OB_GTL;
    uint32_t stg  = sb + OB_STG;

    int b  = blockIdx.y;
    int r0 = blockIdx.x * 64;
    int tid = threadIdx.x;
    int lane = tid & 31, wid = tid >> 5;
    int tx = tid & 15, ty = tid >> 4;
    int grp = lane >> 2, t4 = lane & 3;

    float* Wp = g_W + ((long)b*DH + r0)*DH;
    __nv_bfloat16* WhiP = g_Whi + ((long)b*DH + r0)*DH;
    __nv_bfloat16* WloP = g_Wlo + ((long)b*DH + r0)*DH;
    if (tid < 64) bsh[tid] = b0[r0 + tid];
    __syncthreads();

    int wm = (wid & 3) * 32, wn = (wid >> 2) * 32;    // phase1 layout
    int wm4 = (wid & 3) * 16, wn4 = (wid >> 2) * 32;  // phase4 layout

    for (int c = 0; c < NCH; c++) {
        const __nv_bfloat16* KhC = g_Khi + ((long)b*SEQ + c*CT)*DH;
        const __nv_bfloat16* KlC = g_Klo + ((long)b*SEQ + c*CT)*DH;
        const __nv_bfloat16* QhC = g_Qhi + ((long)b*SEQ + c*CT)*DH;
        const __nv_bfloat16* QlC = g_Qlo + ((long)b*SEQ + c*CT)*DH;
        const float* Vc  = g_V  + ((long)b*SEQ + c*CT)*DH;
        const float* gTi = g_Ti + (((long)b*NCH + c)*CT)*CT;
        const float* gMT = g_MT + (((long)b*NCH + c)*CT)*CT;

        // ---- phase1 stage loader: A=[Khi;Qhi]/[Klo;Qlo], B=Whi/Wlo ----
        auto load_stage1 = [&](int ks, int st) {
            uint32_t base = stg + st*ST1;
            int kb = ks * 64;
            #pragma unroll
            for (int p = 0; p < 8; p++) {
                int id = tid + p*256;
                int arr = id >> 10, rem = id & 1023;
                int row = rem >> 3, ch = rem & 7;
                const __nv_bfloat16* src;
                if (arr == 0) src = (row < 64) ? (KhC + (long)row*DH) : (QhC + (long)(row-64)*DH);
                else          src = (row < 64) ? (KlC + (long)row*DH) : (QlC + (long)(row-64)*DH);
                cp16(base + arr*16384 + SW128((uint32_t)(row*128 + ch*16)),
                     src + kb + ch*8);
            }
            #pragma unroll
            for (int p = 0; p < 4; p++) {
                int id = tid + p*256;
                int arr = id >> 9, rem = id & 511;
                int row = rem >> 3, ch = rem & 7;
                const __nv_bfloat16* src = (arr ? WloP : WhiP) + (long)row*DH + kb + ch*8;
                cp16(base + 32768 + arr*8192 + SW128((uint32_t)(row*128 + ch*16)), src);
            }
            CP_COMMIT();
        };

        // ---- load Tinv^T / M~^T (plain) ----
        for (int idx = tid; idx < CT*CT; idx += 256) {
            int s = idx >> 6, t = idx & 63;
            sTi[s*68 + t] = gTi[idx];
            sMT[s*68 + t] = gMT[idx];
        }

        // ---- phase 1: [U;P] = [Kc;Qc] @ Wslice^T via mma.sync ----
        float c1[2][4][4];
        #pragma unroll
        for (int im = 0; im < 2; im++)
            #pragma unroll
            for (int in = 0; in < 4; in++)
                #pragma unroll
                for (int k = 0; k < 4; k++) c1[im][in][k] = 0.f;

        load_stage1(0, 0);
        for (int ks = 0; ks < 16; ks++) {
            int st = ks & 1;
            if (ks + 1 < 16) { load_stage1(ks + 1, st ^ 1); CP_WAIT(1); }
            else             { CP_WAIT(0); }
            __syncthreads();
            uint32_t Ah = stg + st*ST1, Al = Ah + 16384;
            uint32_t Bh = Ah + 32768,   Bl = Ah + 40960;
            #pragma unroll
            for (int pass = 0; pass < 3; pass++) {
                uint32_t Ab = (pass == 1) ? Al : Ah;
                uint32_t Bb = (pass == 2) ? Bl : Bh;
                #pragma unroll
                for (int kk = 0; kk < 4; kk++) {
                    uint32_t af[2][4];
                    #pragma unroll
                    for (int im = 0; im < 2; im++) {
                        int t = lane >> 3, ri = lane & 7;
                        int row = wm + im*16 + (t & 1)*8 + ri;
                        ldsm_x4(af[im][0], af[im][1], af[im][2], af[im][3],
                                Ab + SW128((uint32_t)(row*128 + kk*32 + (t >> 1)*16)));
                    }
                    uint32_t bfr[4][2];
                    #pragma unroll
                    for (int in = 0; in < 4; in++) {
                        int l = lane & 15;
                        int t = l >> 3, ni = l & 7;
                        int row = wn + in*8 + ni;
                        ldsm_x2(bfr[in][0], bfr[in][1],
                                Bb + SW128((uint32_t)(row*128 + kk*32 + t*16)));
                    }
                    #pragma unroll
                    for (int im = 0; im < 2; im++)
                        #pragma unroll
                        for (int in = 0; in < 4; in++)
                            mma16816(c1[im][in], af[im], bfr[in]);
                }
            }
            __syncthreads();
        }

        // ---- phase1 epilogue: U / P ----
        #pragma unroll
        for (int im = 0; im < 2; im++) {
            #pragma unroll
            for (int in = 0; in < 4; in++) {
                int rrow = wm + im*16 + grp;
                int n = wn + in*8 + t4*2;
                #pragma unroll
                for (int h = 0; h < 2; h++) {
                    int row2 = rrow + h*8;
                    float x0 = c1[im][in][h*2], x1 = c1[im][in][h*2+1];
                    if (row2 < 64) {
                        float2 vv = *(const float2*)(Vc + (long)row2*DH + r0 + n);
                        U[row2*68 + n]     = C2*(x0 + bsh[n]   - vv.x);
                        U[row2*68 + n + 1] = C2*(x1 + bsh[n+1] - vv.y);
                    } else {
                        P[(row2-64)*68 + n]     = x0 + bsh[n];
                        P[(row2-64)*68 + n + 1] = x1 + bsh[n+1];
                    }
                }
            }
        }
        __syncthreads();

        // ---- phase 2: G = Tinv @ U (f32x2) ----
        {
            ull ga[4][2];
            #pragma unroll
            for (int i = 0; i < 4; i++) { ga[i][0] = 0ull; ga[i][1] = 0ull; }
            #pragma unroll 4
            for (int s = 0; s < 64; s++) {
                float a[4];
                *(float4*)a = *(const float4*)(sTi + s*68 + ty*4);
                ulonglong2 bq = *(const ulonglong2*)(U + s*68 + tx*4);
                #pragma unroll
                for (int i = 0; i < 4; i++) {
                    ull aa = dupf(a[i]);
                    fma2(ga[i][0], aa, bq.x);
                    fma2(ga[i][1], aa, bq.y);
                }
            }
            #pragma unroll
            for (int i = 0; i < 4; i++) {
                int t = ty*4 + i;
                float2 c0 = unpack2(ga[i][0]), c1_ = unpack2(ga[i][1]);
                *(float4*)(G + t*68 + tx*4) = make_float4(c0.x, c0.y, c1_.x, c1_.y);
            }
        }
        __syncthreads();

        // ---- phase 3: out = P - M~ @ G (f32x2); Gt convert; bias ----
        {
            ull oa[4][2];
            #pragma unroll
            for (int i = 0; i < 4; i++) { oa[i][0] = 0ull; oa[i][1] = 0ull; }
            #pragma unroll 4
            for (int s = 0; s < 64; s++) {
                float a[4];
                *(float4*)a = *(const float4*)(sMT + s*68 + ty*4);
                ulonglong2 bq = *(const ulonglong2*)(G + s*68 + tx*4);
                #pragma unroll
                for (int i = 0; i < 4; i++) {
                    ull aa = dupf(a[i]);
                    fma2(oa[i][0], aa, bq.x);
                    fma2(oa[i][1], aa, bq.y);
                }
            }
            #pragma unroll
            for (int i = 0; i < 4; i++) {
                int t = ty*4 + i;
                float2 c0 = unpack2(oa[i][0]), c1_ = unpack2(oa[i][1]);
                float* op = out + ((long)b*SEQ + c*CT + t)*DH + r0 + tx*4;
                float4 pv = *(const float4*)(P + t*68 + tx*4);
                *(float4*)op = make_float4(pv.x - c0.x, pv.y - c0.y,
                                           pv.z - c1_.x, pv.w - c1_.y);
            }
            // Gt bf16 hi/lo (transposed: [r][t], 128B rows, SW128)
            for (int idx = tid; idx < CT*CT; idx += 256) {
                int t_ = idx >> 6, r_ = idx & 63;
                float g = G[t_*68 + r_];
                __nv_bfloat16 h = __float2bfloat16(g);
                float hf = __bfloat162float(h);
                __nv_bfloat16 l = __float2bfloat16(g - hf);
                uint32_t off = SW128((uint32_t)(r_*128 + t_*2));
                *(__nv_bfloat16*)(smc + OB_GTH + off) = h;
                *(__nv_bfloat16*)(smc + OB_GTL + off) = l;
            }
            if (tid < 64) {
                float sumg = 0.f;
                #pragma unroll 8
                for (int t = 0; t < 64; t++) sumg += G[t*68 + tid];
                bsh[tid] -= LRATE * sumg;
            }
        }
        __syncthreads();

        // ---- phase 4: Wslice -= LR * G^T @ Kc via mma.sync (16 col-tiles) ----
        auto load_k = [&](int jt, int st) {
            uint32_t base = stg + st*ST1;
            #pragma unroll
            for (int p = 0; p < 4; p++) {
                int id = tid + p*256;
                int arr = id >> 9, rem = id & 511;
                int t_ = rem >> 3, ch = rem & 7;
                const __nv_bfloat16* src = (arr ? KlC : KhC) + (long)t_*DH + jt*64 + ch*8;
                cp16(base + arr*8192 + SW128((uint32_t)(t_*128 + ch*16)), src);
            }
            CP_COMMIT();
        };

        load_k(0, 0);
        for (int jt = 0; jt < 16; jt++) {
            int st = jt & 1;
            if (jt + 1 < 16) { load_k(jt + 1, st ^ 1); CP_WAIT(1); }
            else             { CP_WAIT(0); }
            __syncthreads();
            float c4[4][4];
            #pragma unroll
            for (int in = 0; in < 4; in++)
                #pragma unroll
                for (int k = 0; k < 4; k++) c4[in][k] = 0.f;
            uint32_t Kh = stg + st*ST1, Kl = Kh + 8192;
            #pragma unroll
            for (int pass = 0; pass < 3; pass++) {
                uint32_t Ab = (pass == 1) ? gtl : gth;
                uint32_t Bb = (pass == 2) ? Kl : Kh;
                #pragma unroll
                for (int kk = 0; kk < 4; kk++) {
                    uint32_t af[4];
                    {
                        int t = lane >> 3, ri = lane & 7;
                        int row = wm4 + (t & 1)*8 + ri;
                        ldsm_x4(af[0], af[1], af[2], af[3],
                                Ab + SW128((uint32_t)(row*128 + kk*32 + (t >> 1)*16)));
                    }
                    #pragma unroll
                    for (int in = 0; in < 4; in++) {
                        uint32_t b0r, b1r;
                        int trow = kk*16 + (lane & 15);
                        ldsm_x2t(b0r, b1r,
                                 Bb + SW128((uint32_t)(trow*128 + (wn4 + in*8)*2)));
                        uint32_t bfr[2] = {b0r, b1r};
                        mma16816(c4[in], af, bfr);
                    }
                }
            }
            // epilogue: RMW fp32 W + refresh bf16 hi/lo
            #pragma unroll
            for (int in = 0; in < 4; in++) {
                int colg = jt*64 + wn4 + in*8 + t4*2;
                #pragma unroll
                for (int h = 0; h < 2; h++) {
                    int rw = wm4 + grp + h*8;
                    long idx = (long)rw*DH + colg;
                    float2 w = *(float2*)(Wp + idx);
                    w.x -= LRATE * c4[in][h*2+0];
                    w.y -= LRATE * c4[in][h*2+1];
                    *(float2*)(Wp + idx) = w;
                    __nv_bfloat16 h0 = __float2bfloat16(w.x);
                    __nv_bfloat16 h1 = __float2bfloat16(w.y);
                    __nv_bfloat162 hv; hv.x = h0; hv.y = h1;
                    __nv_bfloat162 lv;
                    lv.x = __float2bfloat16(w.x - __bfloat162float(h0));
                    lv.y = __float2bfloat16(w.y - __bfloat162float(h1));
                    *(__nv_bfloat162*)(WhiP + idx) = hv;
                    *(__nv_bfloat162*)(WloP + idx) = lv;
                }
            }
            __syncthreads();
        }
        __syncthreads();
    }
}

// ---------------- launch ------------------------------------------------------
extern "C" void kernel_launch(void* const* d_in, const int* in_sizes, int n_in,
                              void* d_out, int out_size) {
    const float* in_seq = (const float*)d_in[0];
    const float* tK = (const float*)d_in[1];
    const float* tV = (const float*)d_in[2];
    const float* tQ = (const float*)d_in[3];
    const float* W0 = (const float*)d_in[4];
    const float* b0 = (const float*)d_in[5];
    float* out = (float*)d_out;

    cudaFuncSetAttribute(chunk_fused_kernel,
                         cudaFuncAttributeMaxDynamicSharedMemorySize, CH_SMEM);
    cudaFuncSetAttribute(proj_mma_kernel,
                         cudaFuncAttributeMaxDynamicSharedMemorySize, PROJ_SMEM);

    cvt_kernel<<<(NB*SEQ*DH)/256, 256>>>(in_seq, tK, tV, tQ);
    init_state_kernel<<<(DH*DH)/256, 256>>>(W0);
    proj_mma_kernel<<<dim3((NB*SEQ)/128, DH/64, 3), 256, PROJ_SMEM>>>();
    am_kernel<<<dim3(NCH, NB), 256>>>();
    tinv_kernel<<<dim3(NCH, NB), 64>>>();
    chunk_fused_kernel<<<dim3(DH/64, NB), 256, CH_SMEM>>>(out, b0);
}

// round 8
// speedup vs baseline: 2.5821x; 1.1411x over previous
#include <cuda_runtime.h>
#include <cuda_bf16.h>
#include <cstdint>

#define NB 8
#define SEQ 2048
#define DH 1024
#define CT 64               // chunk length T
#define NCH (SEQ/CT)        // 32 chunks
#define LRATE 0.01f
#define C2 (2.0f/1024.0f)

// ---------------- scratch (static device globals; no allocation) -------------
__device__ float g_V[NB*SEQ*DH];
__device__ float g_W[NB*DH*DH];         // fp32 master inner weights
__device__ float g_A[NB*NCH*CT*CT];
__device__ float g_MT[NB*NCH*CT*CT];
__device__ float g_Ti[NB*NCH*CT*CT];
__device__ __nv_bfloat16 g_Xhi[NB*SEQ*DH];
__device__ __nv_bfloat16 g_Xlo[NB*SEQ*DH];
__device__ __nv_bfloat16 g_Thi[3*DH*DH];
__device__ __nv_bfloat16 g_Tlo[3*DH*DH];
__device__ __nv_bfloat16 g_Khi[NB*SEQ*DH];
__device__ __nv_bfloat16 g_Klo[NB*SEQ*DH];
__device__ __nv_bfloat16 g_Qhi[NB*SEQ*DH];
__device__ __nv_bfloat16 g_Qlo[NB*SEQ*DH];
__device__ __nv_bfloat16 g_Whi[NB*DH*DH];
__device__ __nv_bfloat16 g_Wlo[NB*DH*DH];

// ---------------- packed f32x2 helpers ---------------------------------------
typedef unsigned long long ull;
__device__ __forceinline__ void fma2(ull& c, ull a, ull b) {
    asm("fma.rn.f32x2 %0, %1, %2, %0;" : "+l"(c) : "l"(a), "l"(b));
}
__device__ __forceinline__ ull dupf(float a) {
    ull r; asm("mov.b64 %0, {%1, %1};" : "=l"(r) : "f"(a)); return r;
}
__device__ __forceinline__ float2 unpack2(ull v) {
    float2 f; asm("mov.b64 {%0, %1}, %2;" : "=f"(f.x), "=f"(f.y) : "l"(v)); return f;
}

// ---------------- mma.sync helpers -------------------------------------------
__device__ __forceinline__ uint32_t smem_u32(const void* p) {
    uint32_t a;
    asm("{ .reg .u64 t; cvta.to.shared.u64 t, %1; cvt.u32.u64 %0, t; }"
        : "=r"(a) : "l"(p));
    return a;
}
#define SW128(off) ((off) ^ (((off) >> 3) & 0x70))

__device__ __forceinline__ void ldsm_x4(uint32_t* r, uint32_t a) {
    asm volatile("ldmatrix.sync.aligned.m8n8.x4.shared.b16 {%0,%1,%2,%3}, [%4];"
                 : "=r"(r[0]), "=r"(r[1]), "=r"(r[2]), "=r"(r[3]) : "r"(a));
}
__device__ __forceinline__ void ldsm_x4t(uint32_t* r, uint32_t a) {
    asm volatile("ldmatrix.sync.aligned.m8n8.x4.trans.shared.b16 {%0,%1,%2,%3}, [%4];"
                 : "=r"(r[0]), "=r"(r[1]), "=r"(r[2]), "=r"(r[3]) : "r"(a));
}
__device__ __forceinline__ void mma16816(float* c, const uint32_t* a, const uint32_t* b) {
    asm volatile(
        "mma.sync.aligned.m16n8k16.row.col.f32.bf16.bf16.f32 "
        "{%0,%1,%2,%3}, {%4,%5,%6,%7}, {%8,%9}, {%0,%1,%2,%3};"
        : "+f"(c[0]), "+f"(c[1]), "+f"(c[2]), "+f"(c[3])
        : "r"(a[0]), "r"(a[1]), "r"(a[2]), "r"(a[3]), "r"(b[0]), "r"(b[1]));
}
__device__ __forceinline__ void cp16(uint32_t dst, const void* src) {
    asm volatile("cp.async.cg.shared.global [%0], [%1], 16;"
                 :: "r"(dst), "l"(src) : "memory");
}
#define CP_COMMIT() asm volatile("cp.async.commit_group;" ::: "memory")
#define CP_WAIT(n)  asm volatile("cp.async.wait_group %0;" :: "n"(n) : "memory")

// ---------------- convert inputs to bf16 hi/lo --------------------------------
__global__ void cvt_kernel(const float* __restrict__ X, const float* __restrict__ tK,
                           const float* __restrict__ tV, const float* __restrict__ tQ) {
    long i = (long)blockIdx.x * blockDim.x + threadIdx.x;
    if (i < (long)NB*SEQ*DH) {
        float x = X[i];
        __nv_bfloat16 h = __float2bfloat16(x);
        g_Xhi[i] = h;
        g_Xlo[i] = __float2bfloat16(x - __bfloat162float(h));
    }
    if (i < 3L*DH*DH) {
        int z = (int)(i / (DH*DH));
        long r = i - (long)z*DH*DH;
        const float* t = (z == 0) ? tK : (z == 1) ? tV : tQ;
        float x = t[r];
        __nv_bfloat16 h = __float2bfloat16(x);
        g_Thi[i] = h;
        g_Tlo[i] = __float2bfloat16(x - __bfloat162float(h));
    }
}

// ---------------- init: replicate W0 (+hi/lo) across batches -----------------
__global__ void init_state_kernel(const float* __restrict__ W0) {
    int i = blockIdx.x * blockDim.x + threadIdx.x;
    float w = W0[i];
    __nv_bfloat16 h = __float2bfloat16(w);
    __nv_bfloat16 l = __float2bfloat16(w - __bfloat162float(h));
    #pragma unroll
    for (int b = 0; b < NB; b++) {
        g_W  [(long)b*DH*DH + i] = w;
        g_Whi[(long)b*DH*DH + i] = h;
        g_Wlo[(long)b*DH*DH + i] = l;
    }
}

// ------------- mma.sync projection: C[16384,1024] = X @ Theta^T --------------
#define PSTG 49152
#define PROJ_SMEM (2*PSTG + 1024)

__global__ __launch_bounds__(256) void proj_mma_kernel() {
    extern __shared__ char psm[];
    uint32_t sb = (smem_u32(psm) + 1023u) & ~1023u;

    int tid = threadIdx.x, lane = tid & 31, wid = tid >> 5;
    int wm = (wid & 3) * 32, wn = (wid >> 2) * 32;
    long m0 = (long)blockIdx.x * 128;
    int  n0 = blockIdx.y * 64;
    int  z  = blockIdx.z;
    const __nv_bfloat16* Th = g_Thi + (long)z*DH*DH;
    const __nv_bfloat16* Tl = g_Tlo + (long)z*DH*DH;

    float c[2][4][4];
    #pragma unroll
    for (int im = 0; im < 2; im++)
        #pragma unroll
        for (int in = 0; in < 4; in++)
            #pragma unroll
            for (int k = 0; k < 4; k++) c[im][in][k] = 0.f;

    auto load_stage = [&](int ks, int st) {
        uint32_t base = sb + st*PSTG;
        int kb = ks * 64;
        #pragma unroll
        for (int p = 0; p < 4; p++) {
            int id = tid + p*256;
            int row = id >> 3, ch = id & 7;
            uint32_t off = SW128((uint32_t)(row*128 + ch*16));
            long g = (m0 + row)*DH + kb + ch*8;
            cp16(base + off,         g_Xhi + g);
            cp16(base + 16384 + off, g_Xlo + g);
        }
        #pragma unroll
        for (int p = 0; p < 4; p++) {
            int id = tid + p*256;
            int arr = id >> 9, rem = id & 511;
            int row = rem >> 3, ch = rem & 7;
            uint32_t off = SW128((uint32_t)(row*128 + ch*16));
            const __nv_bfloat16* src = (arr == 0) ? Th : Tl;
            cp16(base + 32768 + arr*8192 + off,
                 src + (long)(n0 + row)*DH + kb + ch*8);
        }
        CP_COMMIT();
    };

    load_stage(0, 0);
    for (int ks = 0; ks < 16; ks++) {
        int st = ks & 1;
        if (ks + 1 < 16) { load_stage(ks + 1, st ^ 1); CP_WAIT(1); }
        else             { CP_WAIT(0); }
        __syncthreads();

        uint32_t Ah = sb + st*PSTG, Al = Ah + 16384;
        uint32_t Bh = Ah + 32768,   Bl = Ah + 40960;
        #pragma unroll
        for (int kk = 0; kk < 4; kk++) {
            uint32_t ah[2][4], al[2][4], bh[2][4], bl[2][4];
            #pragma unroll
            for (int im = 0; im < 2; im++) {
                int t = lane >> 3, ri = lane & 7;
                int row = wm + im*16 + (t & 1)*8 + ri;
                uint32_t off = SW128((uint32_t)(row*128 + kk*32 + (t >> 1)*16));
                ldsm_x4(ah[im], Ah + off);
                ldsm_x4(al[im], Al + off);
            }
            #pragma unroll
            for (int ip = 0; ip < 2; ip++) {
                int g = lane >> 3, ri = lane & 7;
                int row = wn + ip*16 + (g >> 1)*8 + ri;
                uint32_t off = SW128((uint32_t)(row*128 + kk*32 + (g & 1)*16));
                ldsm_x4(bh[ip], Bh + off);
                ldsm_x4(bl[ip], Bl + off);
            }
            #pragma unroll
            for (int im = 0; im < 2; im++)
                #pragma unroll
                for (int ip = 0; ip < 2; ip++) {
                    mma16816(c[im][ip*2],   ah[im], &bh[ip][0]);
                    mma16816(c[im][ip*2+1], ah[im], &bh[ip][2]);
                    mma16816(c[im][ip*2],   al[im], &bh[ip][0]);
                    mma16816(c[im][ip*2+1], al[im], &bh[ip][2]);
                    mma16816(c[im][ip*2],   ah[im], &bl[ip][0]);
                    mma16816(c[im][ip*2+1], ah[im], &bl[ip][2]);
                }
        }
        __syncthreads();
    }

    // ---- epilogue: V fp32 (z==1); K/Q bf16 hi/lo (z!=1) ----
    __nv_bfloat16* Hout = (z == 0) ? g_Khi : g_Qhi;
    __nv_bfloat16* Lout = (z == 0) ? g_Klo : g_Qlo;
    int grp = lane >> 2, t4 = lane & 3;
    #pragma unroll
    for (int im = 0; im < 2; im++) {
        #pragma unroll
        for (int in = 0; in < 4; in++) {
            long row = m0 + wm + im*16 + grp;
            int col = n0 + wn + in*8 + t4*2;
            #pragma unroll
            for (int h = 0; h < 2; h++) {
                long idx = (row + h*8)*DH + col;
                float x0 = c[im][in][h*2], x1 = c[im][in][h*2+1];
                if (z == 1) {
                    *(float2*)(g_V + idx) = make_float2(x0, x1);
                } else {
                    __nv_bfloat16 h0 = __float2bfloat16(x0);
                    __nv_bfloat16 h1 = __float2bfloat16(x1);
                    __nv_bfloat162 hv; hv.x = h0; hv.y = h1;
                    __nv_bfloat162 lv;
                    lv.x = __float2bfloat16(x0 - __bfloat162float(h0));
                    lv.y = __float2bfloat16(x1 - __bfloat162float(h1));
                    *(__nv_bfloat162*)(Hout + idx) = hv;
                    *(__nv_bfloat162*)(Lout + idx) = lv;
                }
            }
        }
    }
}

// -------- mma.sync am: A = cA*([K]Kc^T+1); MT = LR*tril(Q Kc^T+1)^T ----------
// A-operand = stacked [Kc;Qc] (128 rows); B-operand = rows 0..63 of same tile.
#define AMSTG 32768
#define AM_SMEM (2*AMSTG + 1024)

__global__ __launch_bounds__(256) void am_mma_kernel() {
    extern __shared__ char amsm[];
    uint32_t sb = (smem_u32(amsm) + 1023u) & ~1023u;
    int c = blockIdx.x, b = blockIdx.y;
    const __nv_bfloat16* KhC = g_Khi + ((long)b*SEQ + c*CT)*DH;
    const __nv_bfloat16* KlC = g_Klo + ((long)b*SEQ + c*CT)*DH;
    const __nv_bfloat16* QhC = g_Qhi + ((long)b*SEQ + c*CT)*DH;
    const __nv_bfloat16* QlC = g_Qlo + ((long)b*SEQ + c*CT)*DH;
    float* Ao = g_A  + (((long)b*NCH + c)*CT)*CT;
    float* Mo = g_MT + (((long)b*NCH + c)*CT)*CT;

    int tid = threadIdx.x, lane = tid & 31, wid = tid >> 5;
    int wm = (wid & 3) * 32, wn = (wid >> 2) * 32;

    float cc[2][4][4];
    #pragma unroll
    for (int im = 0; im < 2; im++)
        #pragma unroll
        for (int in = 0; in < 4; in++)
            #pragma unroll
            for (int k = 0; k < 4; k++) cc[im][in][k] = 0.f;

    auto load_stage = [&](int ks, int st) {
        uint32_t base = sb + st*AMSTG;
        int kb = ks * 64;
        #pragma unroll
        for (int p = 0; p < 8; p++) {
            int id = tid + p*256;
            int arr = id >> 10, rem = id & 1023;
            int row = rem >> 3, ch = rem & 7;
            const __nv_bfloat16* src;
            if (arr == 0) src = (row < 64) ? (KhC + (long)row*DH) : (QhC + (long)(row-64)*DH);
            else          src = (row < 64) ? (KlC + (long)row*DH) : (QlC + (long)(row-64)*DH);
            cp16(base + arr*16384 + SW128((uint32_t)(row*128 + ch*16)),
                 src + kb + ch*8);
        }
        CP_COMMIT();
    };

    load_stage(0, 0);
    for (int ks = 0; ks < 16; ks++) {
        int st = ks & 1;
        if (ks + 1 < 16) { load_stage(ks + 1, st ^ 1); CP_WAIT(1); }
        else             { CP_WAIT(0); }
        __syncthreads();
        uint32_t Ah = sb + st*AMSTG, Al = Ah + 16384;
        #pragma unroll
        for (int kk = 0; kk < 4; kk++) {
            uint32_t ah[2][4], al[2][4], bh[2][4], bl[2][4];
            #pragma unroll
            for (int im = 0; im < 2; im++) {
                int t = lane >> 3, ri = lane & 7;
                int row = wm + im*16 + (t & 1)*8 + ri;
                uint32_t off = SW128((uint32_t)(row*128 + kk*32 + (t >> 1)*16));
                ldsm_x4(ah[im], Ah + off);
                ldsm_x4(al[im], Al + off);
            }
            #pragma unroll
            for (int ip = 0; ip < 2; ip++) {
                int g = lane >> 3, ri = lane & 7;
                int row = wn + ip*16 + (g >> 1)*8 + ri;   // rows 0..63 = Kc
                uint32_t off = SW128((uint32_t)(row*128 + kk*32 + (g & 1)*16));
                ldsm_x4(bh[ip], Ah + off);
                ldsm_x4(bl[ip], Al + off);
            }
            #pragma unroll
            for (int im = 0; im < 2; im++)
                #pragma unroll
                for (int ip = 0; ip < 2; ip++) {
                    mma16816(cc[im][ip*2],   ah[im], &bh[ip][0]);
                    mma16816(cc[im][ip*2+1], ah[im], &bh[ip][2]);
                    mma16816(cc[im][ip*2],   al[im], &bh[ip][0]);
                    mma16816(cc[im][ip*2+1], al[im], &bh[ip][2]);
                    mma16816(cc[im][ip*2],   ah[im], &bl[ip][0]);
                    mma16816(cc[im][ip*2+1], ah[im], &bl[ip][2]);
                }
        }
        __syncthreads();
    }

    const float cA = C2 * LRATE;
    int grp = lane >> 2, t4 = lane & 3;
    #pragma unroll
    for (int im = 0; im < 2; im++) {
        #pragma unroll
        for (int in = 0; in < 4; in++) {
            int s = wn + in*8 + t4*2;
            #pragma unroll
            for (int h = 0; h < 2; h++) {
                int t = wm + im*16 + grp + h*8;
                float v0 = cc[im][in][h*2]   + 1.f;
                float v1 = cc[im][in][h*2+1] + 1.f;
                if (t < 64) {
                    Ao[(long)t*CT + s]     = cA*v0;
                    Ao[(long)t*CT + s + 1] = cA*v1;
                } else {
                    int tp = t - 64;
                    Mo[(long)s*CT + tp]       = (s     <= tp) ? LRATE*v0 : 0.f;
                    Mo[(long)(s+1)*CT + tp]   = (s + 1 <= tp) ? LRATE*v1 : 0.f;
                }
            }
        }
    }
}

// -------- Tinv = (I + strict_lower(A))^{-1}, stored transposed [col][row] ----
__global__ __launch_bounds__(64) void tinv_kernel() {
    int c = blockIdx.x, b = blockIdx.y;
    const float* Ai = g_A  + (((long)b*NCH + c)*CT)*CT;
    float*       To = g_Ti + (((long)b*NCH + c)*CT)*CT;

    __shared__ float sL[CT*CT];
    __shared__ float X[CT*(CT+1)];
    int tid = threadIdx.x;
    for (int idx = tid; idx < CT*CT; idx += 64) sL[idx] = Ai[idx];
    #pragma unroll
    for (int s = 0; s < CT; s++) X[s*(CT+1) + tid] = (s == tid) ? 1.f : 0.f;
    __syncthreads();

    for (int i = 1; i < CT; i++) {
        float xi = 0.f;
        for (int s = 0; s < i; s++) xi -= sL[i*CT + s] * X[s*(CT+1) + tid];
        if (i > tid) X[i*(CT+1) + tid] = xi;
        __syncthreads();
    }
    for (int i = 0; i < CT; i++)
        To[(long)tid*CT + i] = X[i*(CT+1) + tid];
}

// ---------------- fused persistent chunk kernel (tensor-core) ----------------
#define OB_U   0u
#define OB_P   17408u
#define OB_G   34816u
#define OB_TI  52224u
#define OB_MT  69632u
#define OB_BS  87040u
#define OB_GTH 87296u
#define OB_GTL 95488u
#define OB_STG 104448u
#define ST1    49152u
#define CH_SMEM (104448 + 2*49152)

__global__ __launch_bounds__(256) void chunk_fused_kernel(
    float* __restrict__ out, const float* __restrict__ b0) {
    extern __shared__ char smc[];
    float* smf = (float*)smc;
    float* U   = smf + OB_U/4;
    float* P   = smf + OB_P/4;
    float* G   = smf + OB_G/4;
    float* sTi = smf + OB_TI/4;
    float* sMT = smf + OB_MT/4;
    float* bsh = smf + OB_BS/4;
    uint32_t sb   = smem_u32(smc);
    uint32_t gth  = sb + OB_GTH;
    uint32_t gtl  = sb + OB_GTL;
    uint32_t stg  = sb + OB_STG;

    int b  = blockIdx.y;
    int r0 = blockIdx.x * 64;
    int tid = threadIdx.x;
    int lane = tid & 31, wid = tid >> 5;
    int tx = tid & 15, ty = tid >> 4;
    int grp = lane >> 2, t4 = lane & 3;

    float* Wp = g_W + ((long)b*DH + r0)*DH;
    __nv_bfloat16* WhiP = g_Whi + ((long)b*DH + r0)*DH;
    __nv_bfloat16* WloP = g_Wlo + ((long)b*DH + r0)*DH;
    if (tid < 64) bsh[tid] = b0[r0 + tid];
    __syncthreads();

    int wm = (wid & 3) * 32, wn = (wid >> 2) * 32;    // phase1 layout
    int wm4 = (wid & 3) * 16, wn4 = (wid >> 2) * 32;  // phase4 layout

    for (int c = 0; c < NCH; c++) {
        const __nv_bfloat16* KhC = g_Khi + ((long)b*SEQ + c*CT)*DH;
        const __nv_bfloat16* KlC = g_Klo + ((long)b*SEQ + c*CT)*DH;
        const __nv_bfloat16* QhC = g_Qhi + ((long)b*SEQ + c*CT)*DH;
        const __nv_bfloat16* QlC = g_Qlo + ((long)b*SEQ + c*CT)*DH;
        const float* Vc  = g_V  + ((long)b*SEQ + c*CT)*DH;
        const float* gTi = g_Ti + (((long)b*NCH + c)*CT)*CT;
        const float* gMT = g_MT + (((long)b*NCH + c)*CT)*CT;

        auto load_stage1 = [&](int ks, int st) {
            uint32_t base = stg + st*ST1;
            int kb = ks * 64;
            #pragma unroll
            for (int p = 0; p < 8; p++) {
                int id = tid + p*256;
                int arr = id >> 10, rem = id & 1023;
                int row = rem >> 3, ch = rem & 7;
                const __nv_bfloat16* src;
                if (arr == 0) src = (row < 64) ? (KhC + (long)row*DH) : (QhC + (long)(row-64)*DH);
                else          src = (row < 64) ? (KlC + (long)row*DH) : (QlC + (long)(row-64)*DH);
                cp16(base + arr*16384 + SW128((uint32_t)(row*128 + ch*16)),
                     src + kb + ch*8);
            }
            #pragma unroll
            for (int p = 0; p < 4; p++) {
                int id = tid + p*256;
                int arr = id >> 9, rem = id & 511;
                int row = rem >> 3, ch = rem & 7;
                const __nv_bfloat16* src = (arr ? WloP : WhiP) + (long)row*DH + kb + ch*8;
                cp16(base + 32768 + arr*8192 + SW128((uint32_t)(row*128 + ch*16)), src);
            }
            CP_COMMIT();
        };

        for (int idx = tid; idx < CT*CT; idx += 256) {
            int s = idx >> 6, t = idx & 63;
            sTi[s*68 + t] = gTi[idx];
            sMT[s*68 + t] = gMT[idx];
        }

        // ---- phase 1: [U;P] = [Kc;Qc] @ Wslice^T via mma.sync ----
        float c1[2][4][4];
        #pragma unroll
        for (int im = 0; im < 2; im++)
            #pragma unroll
            for (int in = 0; in < 4; in++)
                #pragma unroll
                for (int k = 0; k < 4; k++) c1[im][in][k] = 0.f;

        load_stage1(0, 0);
        for (int ks = 0; ks < 16; ks++) {
            int st = ks & 1;
            if (ks + 1 < 16) { load_stage1(ks + 1, st ^ 1); CP_WAIT(1); }
            else             { CP_WAIT(0); }
            __syncthreads();
            uint32_t Ah = stg + st*ST1, Al = Ah + 16384;
            uint32_t Bh = Ah + 32768,   Bl = Ah + 40960;
            #pragma unroll
            for (int kk = 0; kk < 4; kk++) {
                uint32_t ah[2][4], al[2][4], bh[2][4], bl[2][4];
                #pragma unroll
                for (int im = 0; im < 2; im++) {
                    int t = lane >> 3, ri = lane & 7;
                    int row = wm + im*16 + (t & 1)*8 + ri;
                    uint32_t off = SW128((uint32_t)(row*128 + kk*32 + (t >> 1)*16));
                    ldsm_x4(ah[im], Ah + off);
                    ldsm_x4(al[im], Al + off);
                }
                #pragma unroll
                for (int ip = 0; ip < 2; ip++) {
                    int g = lane >> 3, ri = lane & 7;
                    int row = wn + ip*16 + (g >> 1)*8 + ri;
                    uint32_t off = SW128((uint32_t)(row*128 + kk*32 + (g & 1)*16));
                    ldsm_x4(bh[ip], Bh + off);
                    ldsm_x4(bl[ip], Bl + off);
                }
                #pragma unroll
                for (int im = 0; im < 2; im++)
                    #pragma unroll
                    for (int ip = 0; ip < 2; ip++) {
                        mma16816(c1[im][ip*2],   ah[im], &bh[ip][0]);
                        mma16816(c1[im][ip*2+1], ah[im], &bh[ip][2]);
                        mma16816(c1[im][ip*2],   al[im], &bh[ip][0]);
                        mma16816(c1[im][ip*2+1], al[im], &bh[ip][2]);
                        mma16816(c1[im][ip*2],   ah[im], &bl[ip][0]);
                        mma16816(c1[im][ip*2+1], ah[im], &bl[ip][2]);
                    }
            }
            __syncthreads();
        }

        // ---- phase1 epilogue: U / P ----
        #pragma unroll
        for (int im = 0; im < 2; im++) {
            #pragma unroll
            for (int in = 0; in < 4; in++) {
                int rrow = wm + im*16 + grp;
                int n = wn + in*8 + t4*2;
                #pragma unroll
                for (int h = 0; h < 2; h++) {
                    int row2 = rrow + h*8;
                    float x0 = c1[im][in][h*2], x1 = c1[im][in][h*2+1];
                    if (row2 < 64) {
                        float2 vv = *(const float2*)(Vc + (long)row2*DH + r0 + n);
                        U[row2*68 + n]     = C2*(x0 + bsh[n]   - vv.x);
                        U[row2*68 + n + 1] = C2*(x1 + bsh[n+1] - vv.y);
                    } else {
                        P[(row2-64)*68 + n]     = x0 + bsh[n];
                        P[(row2-64)*68 + n + 1] = x1 + bsh[n+1];
                    }
                }
            }
        }
        __syncthreads();

        // ---- phase 2: G = Tinv @ U (f32x2) ----
        {
            ull ga[4][2];
            #pragma unroll
            for (int i = 0; i < 4; i++) { ga[i][0] = 0ull; ga[i][1] = 0ull; }
            #pragma unroll 4
            for (int s = 0; s < 64; s++) {
                float a[4];
                *(float4*)a = *(const float4*)(sTi + s*68 + ty*4);
                ulonglong2 bq = *(const ulonglong2*)(U + s*68 + tx*4);
                #pragma unroll
                for (int i = 0; i < 4; i++) {
                    ull aa = dupf(a[i]);
                    fma2(ga[i][0], aa, bq.x);
                    fma2(ga[i][1], aa, bq.y);
                }
            }
            #pragma unroll
            for (int i = 0; i < 4; i++) {
                int t = ty*4 + i;
                float2 c0 = unpack2(ga[i][0]), c1_ = unpack2(ga[i][1]);
                *(float4*)(G + t*68 + tx*4) = make_float4(c0.x, c0.y, c1_.x, c1_.y);
            }
        }
        __syncthreads();

        // ---- phase 3: out = P - M~ @ G (f32x2); Gt convert; bias ----
        {
            ull oa[4][2];
            #pragma unroll
            for (int i = 0; i < 4; i++) { oa[i][0] = 0ull; oa[i][1] = 0ull; }
            #pragma unroll 4
            for (int s = 0; s < 64; s++) {
                float a[4];
                *(float4*)a = *(const float4*)(sMT + s*68 + ty*4);
                ulonglong2 bq = *(const ulonglong2*)(G + s*68 + tx*4);
                #pragma unroll
                for (int i = 0; i < 4; i++) {
                    ull aa = dupf(a[i]);
                    fma2(oa[i][0], aa, bq.x);
                    fma2(oa[i][1], aa, bq.y);
                }
            }
            #pragma unroll
            for (int i = 0; i < 4; i++) {
                int t = ty*4 + i;
                float2 c0 = unpack2(oa[i][0]), c1_ = unpack2(oa[i][1]);
                float* op = out + ((long)b*SEQ + c*CT + t)*DH + r0 + tx*4;
                float4 pv = *(const float4*)(P + t*68 + tx*4);
                *(float4*)op = make_float4(pv.x - c0.x, pv.y - c0.y,
                                           pv.z - c1_.x, pv.w - c1_.y);
            }
            for (int idx = tid; idx < CT*CT; idx += 256) {
                int t_ = idx >> 6, r_ = idx & 63;
                float g = G[t_*68 + r_];
                __nv_bfloat16 h = __float2bfloat16(g);
                float hf = __bfloat162float(h);
                __nv_bfloat16 l = __float2bfloat16(g - hf);
                uint32_t off = SW128((uint32_t)(r_*128 + t_*2));
                *(__nv_bfloat16*)(smc + OB_GTH + off) = h;
                *(__nv_bfloat16*)(smc + OB_GTL + off) = l;
            }
            if (tid < 64) {
                float sumg = 0.f;
                #pragma unroll 8
                for (int t = 0; t < 64; t++) sumg += G[t*68 + tid];
                bsh[tid] -= LRATE * sumg;
            }
        }
        __syncthreads();

        // ---- phase 4: Wslice -= LR * G^T @ Kc via mma.sync (16 col-tiles) ----
        // Preload invariant A-fragments (G^T hi/lo) once.
        uint32_t afh[4][4], afl[4][4];
        #pragma unroll
        for (int kk = 0; kk < 4; kk++) {
            int t = lane >> 3, ri = lane & 7;
            int row = wm4 + (t & 1)*8 + ri;
            uint32_t off = SW128((uint32_t)(row*128 + kk*32 + (t >> 1)*16));
            ldsm_x4(afh[kk], gth + off);
            ldsm_x4(afl[kk], gtl + off);
        }

        auto load_k = [&](int jt, int st) {
            uint32_t base = stg + st*ST1;
            #pragma unroll
            for (int p = 0; p < 4; p++) {
                int id = tid + p*256;
                int arr = id >> 9, rem = id & 511;
                int t_ = rem >> 3, ch = rem & 7;
                const __nv_bfloat16* src = (arr ? KlC : KhC) + (long)t_*DH + jt*64 + ch*8;
                cp16(base + arr*8192 + SW128((uint32_t)(t_*128 + ch*16)), src);
            }
            CP_COMMIT();
        };

        load_k(0, 0);
        for (int jt = 0; jt < 16; jt++) {
            int st = jt & 1;
            if (jt + 1 < 16) { load_k(jt + 1, st ^ 1); CP_WAIT(1); }
            else             { CP_WAIT(0); }
            __syncthreads();
            float c4[4][4];
            #pragma unroll
            for (int in = 0; in < 4; in++)
                #pragma unroll
                for (int k = 0; k < 4; k++) c4[in][k] = 0.f;
            uint32_t Kh = stg + st*ST1, Kl = Kh + 8192;
            #pragma unroll
            for (int kk = 0; kk < 4; kk++) {
                uint32_t bh[2][4], bl[2][4];
                #pragma unroll
                for (int ip = 0; ip < 2; ip++) {
                    int g = lane >> 3;
                    int row = kk*16 + (g & 1)*8 + (lane & 7);
                    uint32_t off = SW128((uint32_t)(row*128 + (wn4 + (ip*2 + (g >> 1))*8)*2));
                    ldsm_x4t(bh[ip], Kh + off);
                    ldsm_x4t(bl[ip], Kl + off);
                }
                #pragma unroll
                for (int ip = 0; ip < 2; ip++)
                    #pragma unroll
                    for (int q = 0; q < 2; q++) {
                        int in = ip*2 + q;
                        mma16816(c4[in], afh[kk], &bh[ip][q*2]);
                        mma16816(c4[in], afl[kk], &bh[ip][q*2]);
                        mma16816(c4[in], afh[kk], &bl[ip][q*2]);
                    }
            }
            // epilogue: RMW fp32 W + refresh bf16 hi/lo
            #pragma unroll
            for (int in = 0; in < 4; in++) {
                int colg = jt*64 + wn4 + in*8 + t4*2;
                #pragma unroll
                for (int h = 0; h < 2; h++) {
                    int rw = wm4 + grp + h*8;
                    long idx = (long)rw*DH + colg;
                    float2 w = *(float2*)(Wp + idx);
                    w.x -= LRATE * c4[in][h*2+0];
                    w.y -= LRATE * c4[in][h*2+1];
                    *(float2*)(Wp + idx) = w;
                    __nv_bfloat16 h0 = __float2bfloat16(w.x);
                    __nv_bfloat16 h1 = __float2bfloat16(w.y);
                    __nv_bfloat162 hv; hv.x = h0; hv.y = h1;
                    __nv_bfloat162 lv;
                    lv.x = __float2bfloat16(w.x - __bfloat162float(h0));
                    lv.y = __float2bfloat16(w.y - __bfloat162float(h1));
                    *(__nv_bfloat162*)(WhiP + idx) = hv;
                    *(__nv_bfloat162*)(WloP + idx) = lv;
                }
            }
            __syncthreads();
        }
        __syncthreads();
    }
}

// ---------------- launch ------------------------------------------------------
extern "C" void kernel_launch(void* const* d_in, const int* in_sizes, int n_in,
                              void* d_out, int out_size) {
    const float* in_seq = (const float*)d_in[0];
    const float* tK = (const float*)d_in[1];
    const float* tV = (const float*)d_in[2];
    const float* tQ = (const float*)d_in[3];
    const float* W0 = (const float*)d_in[4];
    const float* b0 = (const float*)d_in[5];
    float* out = (float*)d_out;

    cudaFuncSetAttribute(chunk_fused_kernel,
                         cudaFuncAttributeMaxDynamicSharedMemorySize, CH_SMEM);
    cudaFuncSetAttribute(proj_mma_kernel,
                         cudaFuncAttributeMaxDynamicSharedMemorySize, PROJ_SMEM);
    cudaFuncSetAttribute(am_mma_kernel,
                         cudaFuncAttributeMaxDynamicSharedMemorySize, AM_SMEM);

    cvt_kernel<<<(NB*SEQ*DH)/256, 256>>>(in_seq, tK, tV, tQ);
    init_state_kernel<<<(DH*DH)/256, 256>>>(W0);
    proj_mma_kernel<<<dim3((NB*SEQ)/128, DH/64, 3), 256, PROJ_SMEM>>>();
    am_mma_kernel<<<dim3(NCH, NB), 256, AM_SMEM>>>();
    tinv_kernel<<<dim3(NCH, NB), 64>>>();
    chunk_fused_kernel<<<dim3(DH/64, NB), 256, CH_SMEM>>>(out, b0);
}